// round 4
// baseline (speedup 1.0000x reference)
#include <cuda_runtime.h>

#define NN 52      // nodes
#define NE 832     // edges
#define E2 884     // edges + self loops
#define FD 256     // feature dim
#define NT 512     // threads per CTA
#define RS 56      // padded row stride of transposed tile (mult of 4 for LDS.128)

union F2U { float2 f; unsigned long long u; };

__device__ __forceinline__ unsigned long long pack2(float a, float b){
    F2U t; t.f = make_float2(a, b); return t.u;
}
__device__ __forceinline__ float2 unpack2(unsigned long long v){
    F2U t; t.u = v; return t.f;
}
// packed dual-fp32 FMA (sm_100+): d.lo += a.lo*b.lo ; d.hi += a.hi*b.hi
__device__ __forceinline__ void fma2(unsigned long long& d,
                                     unsigned long long a,
                                     unsigned long long b){
    asm("fma.rn.f32x2 %0, %1, %2, %0;" : "+l"(d) : "l"(a), "l"(b));
}
__device__ __forceinline__ float sigmoidf_(float x){
    return 1.f / (1.f + __expf(-x));
}

// shared memory accounting (floats + ints)
constexpr int SM_FLOATS = FD*RS + NN*FD + E2 + NN*5 + FD*5 + NT*2;
constexpr int SM_INTS   = E2*3 + (NN+1) + NN;
constexpr int SMEM_BYTES = (SM_FLOATS + SM_INTS) * 4;

__global__ void __launch_bounds__(NT, 1)
gcab_kernel(const float* __restrict__ xg, const void* __restrict__ eig,
            const float* __restrict__ W0, const float* __restrict__ as0,
            const float* __restrict__ ad0, const float* __restrict__ b0,
            const float* __restrict__ W1, const float* __restrict__ as1,
            const float* __restrict__ ad1, const float* __restrict__ b1,
            const float* __restrict__ Wm, const float* __restrict__ bm,
            const float* __restrict__ wgp, const float* __restrict__ bgp,
            float* __restrict__ outg)
{
    extern __shared__ float sm[];
    float* sAT   = sm;                 // [256][56] transposed activations (x -> h0 -> h)
    float* sB    = sAT + FD*RS;        // [52][256] xp (row-major)
    float* sAl   = sB + NN*FD;         // [884] edge logits -> alpha
    float* sAsrc = sAl + E2;           // [52]
    float* sAdst = sAsrc + NN;         // [52]
    float* sHmax = sAdst + NN;         // [52]
    float* sDinv = sHmax + NN;         // [52]
    float* sMno  = sDinv + NN;         // [52]
    float* sAs   = sMno + NN;          // [256]
    float* sAd   = sAs + FD;           // [256]
    float* sAvg  = sAd + FD;           // [256]
    float* sMx   = sAvg + FD;          // [256]
    float* sMch  = sMx + FD;           // [256]
    float* sPa   = sMch + FD;          // [512] scratch partial
    float* sPm   = sPa + NT;           // [512] scratch partial
    int*   sS    = (int*)(sPm + NT);   // [884] src
    int*   sD    = sS + E2;            // [884] dst
    int*   sIdx  = sD + E2;            // [884] CSR edge ids
    int*   sOff  = sIdx + E2;          // [53]
    int*   sCnt  = sOff + (NN+1);      // [52]
    __shared__ int sIs64;

    const int tid  = threadIdx.x;
    const int g    = blockIdx.x;
    const int lane = tid & 31, wrp = tid >> 5;

    // ------- detect edge_index dtype (int64 vs int32) -------
    if (tid == 0){
        const int* e32 = (const int*)eig;
        int flag = 1;
        #pragma unroll 1
        for (int i = 0; i < 32; i++){
            if (e32[2*i + 1] != 0){ flag = 0; break; }
        }
        sIs64 = flag;
    }

    // ---------------- load x transposed directly ----------------
    {
        const float* xr = xg + (size_t)g*NN*FD;
        for (int i = tid; i < NN*FD; i += NT){
            int r = i >> 8;           // row
            int f = i & 255;          // feature (consecutive per lane -> coalesced LDG)
            sAT[f*RS + r] = xr[i];
        }
        if (tid < NN) sCnt[tid] = 0;
    }
    __syncthreads();

    // ---------------- load edges ----------------
    {
        const int is64 = sIs64;
        const long long* ei64 = (const long long*)eig + (size_t)g*2*NE;
        const int*       ei32 = (const int*)eig       + (size_t)g*2*NE;
        for (int e = tid; e < E2; e += NT){
            int s, d;
            if (e < NE){
                if (is64){ s = (int)ei64[e]; d = (int)ei64[NE + e]; }
                else     { s = ei32[e];      d = ei32[NE + e]; }
            } else {
                s = e - NE; d = e - NE;
            }
            sS[e] = s; sD[e] = d;
        }
    }
    __syncthreads();
    for (int e = tid; e < E2; e += NT) atomicAdd(&sCnt[sD[e]], 1);
    __syncthreads();
    if (tid == 0){
        int acc = 0;
        for (int i = 0; i < NN; i++){ sOff[i] = acc; acc += sCnt[i]; }
        sOff[NN] = acc;
    }
    __syncthreads();
    // deterministic CSR fill via warp ballot (edge order preserved)
    for (int nd = wrp; nd < NN; nd += 16){
        int pos = sOff[nd];
        for (int base = 0; base < E2; base += 32){
            int e = base + lane;
            bool m = (e < E2) && (sD[e] == nd);
            unsigned mask = __ballot_sync(0xffffffffu, m);
            if (m){
                int r = __popc(mask & ((1u << lane) - 1u));
                sIdx[pos + r] = e;
            }
            pos += __popc(mask);
        }
    }
    if (tid < NN) sDinv[tid] = rsqrtf((float)sCnt[tid]);
    __syncthreads();

    // GEMM thread mapping
    const int cg = tid & 127;        // column pair: cols 2cg, 2cg+1
    const int rg = (tid >> 7) & 1;   // row group: rg0 rows 0..27 (7 quads), rg1 rows 28..51 (6 quads)
    const int kh = tid >> 8;         // k half

    // ---------------- two GAT rounds ----------------
    for (int rnd = 0; rnd < 2; rnd++){
        const float* W  = rnd ? W1  : W0;
        const float* av = rnd ? as1 : as0;
        const float* dv = rnd ? ad1 : ad0;
        const float* bb = rnd ? b1  : b0;
        for (int i = tid; i < FD; i += NT){ sAs[i] = av[i]; sAd[i] = dv[i]; }

        // GEMM: sB[52][256] = A[52][256] @ W[256][256]
        {
            unsigned long long acc[14][2];
#pragma unroll
            for (int i = 0; i < 14; i++){ acc[i][0] = 0ull; acc[i][1] = 0ull; }
            const float* wp = W + (size_t)(kh*128)*FD + 2*cg;
            const float* xb = sAT + (kh*128)*RS + rg*28;
            if (rg == 0){
#pragma unroll 2
                for (int kk = 0; kk < 128; kk++){
                    float2 w = *reinterpret_cast<const float2*>(wp); wp += FD;
                    unsigned long long w0 = pack2(w.x, w.x);
                    unsigned long long w1 = pack2(w.y, w.y);
                    const float4* xr4 = reinterpret_cast<const float4*>(xb); xb += RS;
#pragma unroll
                    for (int j = 0; j < 7; j++){
                        float4 xv = xr4[j];
                        unsigned long long lo = pack2(xv.x, xv.y);
                        unsigned long long hi = pack2(xv.z, xv.w);
                        fma2(acc[2*j  ][0], lo, w0); fma2(acc[2*j  ][1], lo, w1);
                        fma2(acc[2*j+1][0], hi, w0); fma2(acc[2*j+1][1], hi, w1);
                    }
                }
            } else {
#pragma unroll 2
                for (int kk = 0; kk < 128; kk++){
                    float2 w = *reinterpret_cast<const float2*>(wp); wp += FD;
                    unsigned long long w0 = pack2(w.x, w.x);
                    unsigned long long w1 = pack2(w.y, w.y);
                    const float4* xr4 = reinterpret_cast<const float4*>(xb); xb += RS;
#pragma unroll
                    for (int j = 0; j < 6; j++){
                        float4 xv = xr4[j];
                        unsigned long long lo = pack2(xv.x, xv.y);
                        unsigned long long hi = pack2(xv.z, xv.w);
                        fma2(acc[2*j  ][0], lo, w0); fma2(acc[2*j  ][1], lo, w1);
                        fma2(acc[2*j+1][0], hi, w0); fma2(acc[2*j+1][1], hi, w1);
                    }
                }
            }
            const int np = (rg == 0) ? 14 : 12;
            const int rb = rg * 28;
            // k-half 0 writes, k-half 1 accumulates
            if (kh == 0){
                for (int i = 0; i < np; i++){
                    float2 c0 = unpack2(acc[i][0]);
                    float2 c1 = unpack2(acc[i][1]);
                    int r0 = rb + 2*i;
                    reinterpret_cast<float2*>(sB + r0*FD)[cg]     = make_float2(c0.x, c1.x);
                    reinterpret_cast<float2*>(sB + (r0+1)*FD)[cg] = make_float2(c0.y, c1.y);
                }
            }
            __syncthreads();
            if (kh == 1){
                for (int i = 0; i < np; i++){
                    float2 c0 = unpack2(acc[i][0]);
                    float2 c1 = unpack2(acc[i][1]);
                    int r0 = rb + 2*i;
                    float2* p0 = &reinterpret_cast<float2*>(sB + r0*FD)[cg];
                    float2* p1 = &reinterpret_cast<float2*>(sB + (r0+1)*FD)[cg];
                    float2 o0 = *p0, o1 = *p1;
                    *p0 = make_float2(o0.x + c0.x, o0.y + c1.x);
                    *p1 = make_float2(o1.x + c0.y, o1.y + c1.y);
                }
            }
            __syncthreads();
        }

        // asrc/adst per row: warp-per-row reductions (16 warps)
        for (int r = wrp; r < NN; r += 16){
            float sa = 0.f, sd = 0.f;
#pragma unroll
            for (int t = 0; t < 8; t++){
                float v = sB[r*FD + lane + 32*t];
                sa += v * sAs[lane + 32*t];
                sd += v * sAd[lane + 32*t];
            }
#pragma unroll
            for (int o = 16; o; o >>= 1){
                sa += __shfl_down_sync(0xffffffffu, sa, o);
                sd += __shfl_down_sync(0xffffffffu, sd, o);
            }
            if (lane == 0){ sAsrc[r] = sa; sAdst[r] = sd; }
        }
        __syncthreads();

        // fused logits + per-dest softmax: warp per node, lanes over edges
        for (int nd = wrp; nd < NN; nd += 16){
            int beg = sOff[nd], end = sOff[nd+1];
            float m = -3.0e38f;
            for (int t = beg + lane; t < end; t += 32){
                int e = sIdx[t];
                float el = sAsrc[sS[e]] + sAdst[nd];
                el = el > 0.f ? el : 0.2f * el;
                sAl[e] = el;
                m = fmaxf(m, el);
            }
#pragma unroll
            for (int o = 16; o; o >>= 1)
                m = fmaxf(m, __shfl_xor_sync(0xffffffffu, m, o));
            float s = 0.f;
            for (int t = beg + lane; t < end; t += 32){
                int e = sIdx[t];
                float w = __expf(sAl[e] - m);
                sAl[e] = w;
                s += w;
            }
#pragma unroll
            for (int o = 16; o; o >>= 1)
                s += __shfl_xor_sync(0xffffffffu, s, o);
            float inv = 1.f / s;
            for (int t = beg + lane; t < end; t += 32)
                sAl[sIdx[t]] *= inv;
        }
        __syncthreads();

        // aggregation: 128 column-pairs x 4 row quarters; writes transposed sAT
        {
            const int p  = tid & 127;
            const int q  = tid >> 7;          // 0..3
            const float2* sB2 = reinterpret_cast<const float2*>(sB);
            float2 bbv = reinterpret_cast<const float2*>(bb)[p];
            for (int dd = q*13; dd < q*13 + 13; dd++){
                int beg = sOff[dd], end = sOff[dd+1];
                unsigned long long acc = 0ull;
                for (int t = beg; t < end; t++){
                    int e  = sIdx[t];
                    float al = sAl[e];
                    F2U xv; xv.f = sB2[sS[e]*(FD/2) + p];
                    fma2(acc, xv.u, pack2(al, al));
                }
                float2 r = unpack2(acc);
                float v0 = r.x + bbv.x;
                float v1 = r.y + bbv.y;
                float* a0 = &sAT[(2*p  )*RS + dd];
                float* a1 = &sAT[(2*p+1)*RS + dd];
                if (rnd == 1){
                    v0 = fmaxf(v0 + *a0, 0.f);
                    v1 = fmaxf(v1 + *a1, 0.f);
                }
                *a0 = v0;
                *a1 = v1;
            }
        }
        __syncthreads();
    }

    // ---------------- channel attention ----------------
    {
        const int j = tid & 255, half = tid >> 8;
        float s = 0.f, m = -3.0e38f;
        for (int r = half*26; r < half*26 + 26; r++){
            float v = sAT[j*RS + r];
            s += v; m = fmaxf(m, v);
        }
        sPa[tid] = s; sPm[tid] = m;
    }
    __syncthreads();
    if (tid < FD){
        sAvg[tid] = (sPa[tid] + sPa[tid + 256]) * (1.f/52.f);
        sMx[tid]  = fmaxf(sPm[tid], sPm[tid + 256]);
    }
    __syncthreads();
    {
        const int j = tid & 255, half = tid >> 8;
        float aA = 0.f, aM = 0.f;
        const float* wc = Wm + j;
#pragma unroll 4
        for (int k = half*128; k < half*128 + 128; k++){
            float w = wc[k*FD];
            aA += sAvg[k]*w;
            aM += sMx[k]*w;
        }
        sPa[tid] = aA; sPm[tid] = aM;
    }
    __syncthreads();
    if (tid < FD){
        float aA = sPa[tid] + sPa[tid + 256];
        float aM = sPm[tid] + sPm[tid + 256];
        float bj = bm[tid];
        sMch[tid] = sigmoidf_(fmaxf(aA + bj, 0.f) + fmaxf(aM + bj, 0.f));
    }
    __syncthreads();

    // ---------------- node attention ----------------
    // row max over (h * mch) — mch folded
    for (int r = wrp; r < NN; r += 16){
        float mx = -3.0e38f;
#pragma unroll
        for (int t = 0; t < 8; t++){
            int f = lane + 32*t;
            mx = fmaxf(mx, sAT[f*RS + r] * sMch[f]);
        }
#pragma unroll
        for (int o = 16; o; o >>= 1)
            mx = fmaxf(mx, __shfl_down_sync(0xffffffffu, mx, o));
        if (lane == 0) sHmax[r] = mx;
    }
    __syncthreads();
    // 1->1 GCN with symmetric norm + sigmoid
    if (tid < NN){
        float s = 0.f;
        int beg = sOff[tid], end = sOff[tid+1];
        for (int t = beg; t < end; t++){
            int ss = sS[sIdx[t]];
            s += sDinv[ss] * sHmax[ss];
        }
        float aggv = sDinv[tid] * s * wgp[0] + bgp[0];
        sMno[tid] = sigmoidf_(aggv);
    }
    __syncthreads();

    // ---------------- final write (mch * mno folded) ----------------
    {
        float* op = outg + (size_t)g*NN*FD;
        for (int i = tid; i < NN*FD; i += NT){
            int r = i >> 8, f = i & 255;
            op[i] = sAT[f*RS + r] * sMch[f] * sMno[r];
        }
    }
}

extern "C" void kernel_launch(void* const* d_in, const int* in_sizes, int n_in,
                              void* d_out, int out_size)
{
    const float* x   = (const float*)d_in[0];
    const void*  ei  = d_in[1];
    const float* W0  = (const float*)d_in[2];
    const float* as0 = (const float*)d_in[3];
    const float* ad0 = (const float*)d_in[4];
    const float* b0  = (const float*)d_in[5];
    const float* W1  = (const float*)d_in[6];
    const float* as1 = (const float*)d_in[7];
    const float* ad1 = (const float*)d_in[8];
    const float* b1  = (const float*)d_in[9];
    const float* Wm  = (const float*)d_in[10];
    const float* bm  = (const float*)d_in[11];
    const float* wg  = (const float*)d_in[12];
    const float* bg  = (const float*)d_in[13];
    float* out = (float*)d_out;

    int B = in_sizes[0] / (NN*FD);

    cudaFuncSetAttribute(gcab_kernel,
                         cudaFuncAttributeMaxDynamicSharedMemorySize,
                         SMEM_BYTES);
    gcab_kernel<<<B, NT, SMEM_BYTES>>>(x, ei, W0, as0, ad0, b0,
                                       W1, as1, ad1, b1, Wm, bm, wg, bg, out);
}

// round 5
// speedup vs baseline: 1.0592x; 1.0592x over previous
#include <cuda_runtime.h>

#define NN 52      // nodes
#define NE 832     // edges
#define E2 884     // edges + self loops
#define FD 256     // feature dim
#define NT 512     // threads per CTA
#define RS 56      // padded row stride of transposed tile

union F2U { float2 f; unsigned long long u; };

__device__ __forceinline__ unsigned long long pack2(float a, float b){
    F2U t; t.f = make_float2(a, b); return t.u;
}
__device__ __forceinline__ float2 unpack2(unsigned long long v){
    F2U t; t.u = v; return t.f;
}
// packed dual-fp32 FMA (sm_100+)
__device__ __forceinline__ void fma2(unsigned long long& d,
                                     unsigned long long a,
                                     unsigned long long b){
    asm("fma.rn.f32x2 %0, %1, %2, %0;" : "+l"(d) : "l"(a), "l"(b));
}
__device__ __forceinline__ float sigmoidf_(float x){
    return 1.f / (1.f + __expf(-x));
}

// shared memory accounting
constexpr int SM_WORDS = FD*RS + NN*FD + E2*2 + NN*5 + FD*5 + NT*2
                       + E2*2 + (NN+1) + NN;
constexpr int SMEM_BYTES = SM_WORDS * 4;

__global__ void __launch_bounds__(NT, 1)
gcab_kernel(const float* __restrict__ xg, const void* __restrict__ eig,
            const float* __restrict__ W0, const float* __restrict__ as0,
            const float* __restrict__ ad0, const float* __restrict__ b0,
            const float* __restrict__ W1, const float* __restrict__ as1,
            const float* __restrict__ ad1, const float* __restrict__ b1,
            const float* __restrict__ Wm, const float* __restrict__ bm,
            const float* __restrict__ wgp, const float* __restrict__ bgp,
            float* __restrict__ outg)
{
    extern __shared__ float sm[];
    float* sAT   = sm;                 // [256][56] transposed activations
    float* sB    = sAT + FD*RS;        // [52][256] xp (row-major)
    int2*  sEC   = (int2*)(sB + NN*FD);// [884] CSR-ordered {src, alpha_bits}
    float* sECf  = (float*)sEC;        // alias for .y float writes
    float* sAsrc = (float*)(sEC + E2); // [52]
    float* sAdst = sAsrc + NN;         // [52]
    float* sHmax = sAdst + NN;         // [52]
    float* sDinv = sHmax + NN;         // [52]
    float* sMno  = sDinv + NN;         // [52]
    float* sAs   = sMno + NN;          // [256]
    float* sAd   = sAs + FD;           // [256]
    float* sAvg  = sAd + FD;           // [256]
    float* sMx   = sAvg + FD;          // [256]
    float* sMch  = sMx + FD;           // [256]
    float* sPa   = sMch + FD;          // [512]
    float* sPm   = sPa + NT;           // [512]
    int*   sS    = (int*)(sPm + NT);   // [884]
    int*   sD    = sS + E2;            // [884]
    int*   sOff  = sD + E2;            // [53]
    int*   sCnt  = sOff + (NN+1);      // [52]
    __shared__ int sIs64;

    const int tid  = threadIdx.x;
    const int g    = blockIdx.x;
    const int lane = tid & 31, wrp = tid >> 5;

    // ------- detect edge_index dtype (int64 vs int32) -------
    if (tid == 0){
        const int* e32 = (const int*)eig;
        int flag = 1;
        #pragma unroll 1
        for (int i = 0; i < 32; i++){
            if (e32[2*i + 1] != 0){ flag = 0; break; }
        }
        sIs64 = flag;
    }

    // ---------------- load x transposed directly ----------------
    {
        const float* xr = xg + (size_t)g*NN*FD;
        for (int i = tid; i < NN*FD; i += NT){
            int r = i >> 8;
            int f = i & 255;
            sAT[f*RS + r] = xr[i];
        }
        if (tid < NN) sCnt[tid] = 0;
    }
    __syncthreads();

    // ---------------- load edges ----------------
    {
        const int is64 = sIs64;
        const long long* ei64 = (const long long*)eig + (size_t)g*2*NE;
        const int*       ei32 = (const int*)eig       + (size_t)g*2*NE;
        for (int e = tid; e < E2; e += NT){
            int s, d;
            if (e < NE){
                if (is64){ s = (int)ei64[e]; d = (int)ei64[NE + e]; }
                else     { s = ei32[e];      d = ei32[NE + e]; }
            } else {
                s = e - NE; d = e - NE;
            }
            sS[e] = s; sD[e] = d;
        }
    }
    __syncthreads();
    for (int e = tid; e < E2; e += NT) atomicAdd(&sCnt[sD[e]], 1);
    __syncthreads();
    if (tid == 0){
        int acc = 0;
        for (int i = 0; i < NN; i++){ sOff[i] = acc; acc += sCnt[i]; }
        sOff[NN] = acc;
    }
    __syncthreads();
    // deterministic CSR fill: 4 nodes per warp, one sD/sS load per chunk
    {
        const int nd0 = wrp, nd1 = wrp+16, nd2 = wrp+32, nd3 = wrp+48;
        int pos0 = sOff[nd0];
        int pos1 = sOff[nd1];
        int pos2 = sOff[nd2];
        int pos3 = (nd3 < NN) ? sOff[nd3] : 0;
        const unsigned lt = (1u << lane) - 1u;
        for (int base = 0; base < E2; base += 32){
            int e = base + lane;
            int d = -1, s = 0;
            if (e < E2){ d = sD[e]; s = sS[e]; }
            unsigned m0 = __ballot_sync(0xffffffffu, d == nd0);
            if (d == nd0) sEC[pos0 + __popc(m0 & lt)].x = s;
            pos0 += __popc(m0);
            unsigned m1 = __ballot_sync(0xffffffffu, d == nd1);
            if (d == nd1) sEC[pos1 + __popc(m1 & lt)].x = s;
            pos1 += __popc(m1);
            unsigned m2 = __ballot_sync(0xffffffffu, d == nd2);
            if (d == nd2) sEC[pos2 + __popc(m2 & lt)].x = s;
            pos2 += __popc(m2);
            unsigned m3 = __ballot_sync(0xffffffffu, d == nd3);
            if (d == nd3) sEC[pos3 + __popc(m3 & lt)].x = s;
            pos3 += __popc(m3);
        }
    }
    if (tid < NN) sDinv[tid] = rsqrtf((float)sCnt[tid]);
    __syncthreads();

    // GEMM thread mapping
    const int cg = tid & 127;        // column pair: cols 2cg, 2cg+1
    const int rg = (tid >> 7) & 1;   // rows rg*26 .. +26 (13 pairs)
    const int kh = tid >> 8;         // k half

    // ---------------- two GAT rounds ----------------
    for (int rnd = 0; rnd < 2; rnd++){
        const float* W  = rnd ? W1  : W0;
        const float* av = rnd ? as1 : as0;
        const float* dv = rnd ? ad1 : ad0;
        const float* bb = rnd ? b1  : b0;
        for (int i = tid; i < FD; i += NT){ sAs[i] = av[i]; sAd[i] = dv[i]; }

        // GEMM: sB[52][256] = A[52][256] @ W[256][256]
        // thread: 13 row-pairs x 2 cols, half of k; W prefetched 2 ahead
        {
            unsigned long long acc[13][2];
#pragma unroll
            for (int i = 0; i < 13; i++){ acc[i][0] = 0ull; acc[i][1] = 0ull; }
            const float* wbase = W + (size_t)(kh*128)*FD + 2*cg;
            const float* xbase = sAT + (kh*128)*RS + rg*26;
            float2 wn0 = *reinterpret_cast<const float2*>(wbase);
            float2 wn1 = *reinterpret_cast<const float2*>(wbase + FD);
#pragma unroll 2
            for (int kk = 0; kk < 128; kk += 2){
                float2 wc0 = wn0, wc1 = wn1;
                int kp = (kk + 2 < 128) ? (kk + 2) : 0;
                wn0 = *reinterpret_cast<const float2*>(wbase + (size_t)kp*FD);
                wn1 = *reinterpret_cast<const float2*>(wbase + (size_t)(kp+1)*FD);

                unsigned long long w00 = pack2(wc0.x, wc0.x);
                unsigned long long w01 = pack2(wc0.y, wc0.y);
                const float2* xr0 = reinterpret_cast<const float2*>(xbase + (size_t)kk*RS);
#pragma unroll
                for (int i = 0; i < 13; i++){
                    F2U xv; xv.f = xr0[i];
                    fma2(acc[i][0], xv.u, w00);
                    fma2(acc[i][1], xv.u, w01);
                }
                unsigned long long w10 = pack2(wc1.x, wc1.x);
                unsigned long long w11 = pack2(wc1.y, wc1.y);
                const float2* xr1 = reinterpret_cast<const float2*>(xbase + (size_t)(kk+1)*RS);
#pragma unroll
                for (int i = 0; i < 13; i++){
                    F2U xv; xv.f = xr1[i];
                    fma2(acc[i][0], xv.u, w10);
                    fma2(acc[i][1], xv.u, w11);
                }
            }
            // k-half 0 writes, k-half 1 accumulates
            if (kh == 0){
#pragma unroll
                for (int i = 0; i < 13; i++){
                    float2 c0 = unpack2(acc[i][0]);
                    float2 c1 = unpack2(acc[i][1]);
                    int r0 = rg*26 + 2*i;
                    reinterpret_cast<float2*>(sB + r0*FD)[cg]     = make_float2(c0.x, c1.x);
                    reinterpret_cast<float2*>(sB + (r0+1)*FD)[cg] = make_float2(c0.y, c1.y);
                }
            }
            __syncthreads();
            if (kh == 1){
#pragma unroll
                for (int i = 0; i < 13; i++){
                    float2 c0 = unpack2(acc[i][0]);
                    float2 c1 = unpack2(acc[i][1]);
                    int r0 = rg*26 + 2*i;
                    float2* p0 = &reinterpret_cast<float2*>(sB + r0*FD)[cg];
                    float2* p1 = &reinterpret_cast<float2*>(sB + (r0+1)*FD)[cg];
                    float2 o0 = *p0, o1 = *p1;
                    *p0 = make_float2(o0.x + c0.x, o0.y + c1.x);
                    *p1 = make_float2(o1.x + c0.y, o1.y + c1.y);
                }
            }
            __syncthreads();
        }

        // asrc/adst per row: warp-per-row reductions (16 warps)
        for (int r = wrp; r < NN; r += 16){
            float sa = 0.f, sd = 0.f;
#pragma unroll
            for (int t = 0; t < 8; t++){
                float v = sB[r*FD + lane + 32*t];
                sa += v * sAs[lane + 32*t];
                sd += v * sAd[lane + 32*t];
            }
#pragma unroll
            for (int o = 16; o; o >>= 1){
                sa += __shfl_down_sync(0xffffffffu, sa, o);
                sd += __shfl_down_sync(0xffffffffu, sd, o);
            }
            if (lane == 0){ sAsrc[r] = sa; sAdst[r] = sd; }
        }
        __syncthreads();

        // fused logits + per-dest softmax on CSR slots: warp per node
        for (int nd = wrp; nd < NN; nd += 16){
            int beg = sOff[nd], end = sOff[nd+1];
            float adn = sAdst[nd];
            float m = -3.0e38f;
            for (int t = beg + lane; t < end; t += 32){
                int src = sEC[t].x;
                float el = sAsrc[src] + adn;
                el = el > 0.f ? el : 0.2f * el;
                sECf[2*t+1] = el;
                m = fmaxf(m, el);
            }
#pragma unroll
            for (int o = 16; o; o >>= 1)
                m = fmaxf(m, __shfl_xor_sync(0xffffffffu, m, o));
            float s = 0.f;
            for (int t = beg + lane; t < end; t += 32){
                float w = __expf(sECf[2*t+1] - m);
                sECf[2*t+1] = w;
                s += w;
            }
#pragma unroll
            for (int o = 16; o; o >>= 1)
                s += __shfl_xor_sync(0xffffffffu, s, o);
            float inv = 1.f / s;
            for (int t = beg + lane; t < end; t += 32)
                sECf[2*t+1] *= inv;
        }
        __syncthreads();

        // aggregation: 128 column-pairs x 4 row quarters; writes transposed sAT
        {
            const int p  = tid & 127;
            const int q  = tid >> 7;
            const float2* sB2 = reinterpret_cast<const float2*>(sB);
            float2 bbv = reinterpret_cast<const float2*>(bb)[p];
            for (int dd = q*13; dd < q*13 + 13; dd++){
                int beg = sOff[dd], end = sOff[dd+1];
                unsigned long long acc = 0ull;
                for (int t = beg; t < end; t++){
                    int2 v = sEC[t];
                    float al = __int_as_float(v.y);
                    F2U xv; xv.f = sB2[v.x*(FD/2) + p];
                    fma2(acc, xv.u, pack2(al, al));
                }
                float2 r = unpack2(acc);
                float v0 = r.x + bbv.x;
                float v1 = r.y + bbv.y;
                float* a0 = &sAT[(2*p  )*RS + dd];
                float* a1 = &sAT[(2*p+1)*RS + dd];
                if (rnd == 1){
                    v0 = fmaxf(v0 + *a0, 0.f);
                    v1 = fmaxf(v1 + *a1, 0.f);
                }
                *a0 = v0;
                *a1 = v1;
            }
        }
        __syncthreads();
    }

    // ---------------- channel attention ----------------
    {
        const int j = tid & 255, half = tid >> 8;
        float s = 0.f, m = -3.0e38f;
        for (int r = half*26; r < half*26 + 26; r++){
            float v = sAT[j*RS + r];
            s += v; m = fmaxf(m, v);
        }
        sPa[tid] = s; sPm[tid] = m;
    }
    __syncthreads();
    if (tid < FD){
        sAvg[tid] = (sPa[tid] + sPa[tid + 256]) * (1.f/52.f);
        sMx[tid]  = fmaxf(sPm[tid], sPm[tid + 256]);
    }
    __syncthreads();
    {
        const int j = tid & 255, half = tid >> 8;
        float aA = 0.f, aM = 0.f;
        const float* wc = Wm + j;
#pragma unroll 4
        for (int k = half*128; k < half*128 + 128; k++){
            float w = wc[k*FD];
            aA += sAvg[k]*w;
            aM += sMx[k]*w;
        }
        sPa[tid] = aA; sPm[tid] = aM;
    }
    __syncthreads();
    if (tid < FD){
        float aA = sPa[tid] + sPa[tid + 256];
        float aM = sPm[tid] + sPm[tid + 256];
        float bj = bm[tid];
        sMch[tid] = sigmoidf_(fmaxf(aA + bj, 0.f) + fmaxf(aM + bj, 0.f));
    }
    __syncthreads();

    // ---------------- node attention ----------------
    for (int r = wrp; r < NN; r += 16){
        float mx = -3.0e38f;
#pragma unroll
        for (int t = 0; t < 8; t++){
            int f = lane + 32*t;
            mx = fmaxf(mx, sAT[f*RS + r] * sMch[f]);
        }
#pragma unroll
        for (int o = 16; o; o >>= 1)
            mx = fmaxf(mx, __shfl_down_sync(0xffffffffu, mx, o));
        if (lane == 0) sHmax[r] = mx;
    }
    __syncthreads();
    if (tid < NN){
        float s = 0.f;
        int beg = sOff[tid], end = sOff[tid+1];
        for (int t = beg; t < end; t++){
            int ss = sEC[t].x;
            s += sDinv[ss] * sHmax[ss];
        }
        float aggv = sDinv[tid] * s * wgp[0] + bgp[0];
        sMno[tid] = sigmoidf_(aggv);
    }
    __syncthreads();

    // ---------------- final write (mch * mno folded) ----------------
    {
        float* op = outg + (size_t)g*NN*FD;
        for (int i = tid; i < NN*FD; i += NT){
            int r = i >> 8, f = i & 255;
            op[i] = sAT[f*RS + r] * sMch[f] * sMno[r];
        }
    }
}

extern "C" void kernel_launch(void* const* d_in, const int* in_sizes, int n_in,
                              void* d_out, int out_size)
{
    const float* x   = (const float*)d_in[0];
    const void*  ei  = d_in[1];
    const float* W0  = (const float*)d_in[2];
    const float* as0 = (const float*)d_in[3];
    const float* ad0 = (const float*)d_in[4];
    const float* b0  = (const float*)d_in[5];
    const float* W1  = (const float*)d_in[6];
    const float* as1 = (const float*)d_in[7];
    const float* ad1 = (const float*)d_in[8];
    const float* b1  = (const float*)d_in[9];
    const float* Wm  = (const float*)d_in[10];
    const float* bm  = (const float*)d_in[11];
    const float* wg  = (const float*)d_in[12];
    const float* bg  = (const float*)d_in[13];
    float* out = (float*)d_out;

    int B = in_sizes[0] / (NN*FD);

    cudaFuncSetAttribute(gcab_kernel,
                         cudaFuncAttributeMaxDynamicSharedMemorySize,
                         SMEM_BYTES);
    gcab_kernel<<<B, NT, SMEM_BYTES>>>(x, ei, W0, as0, ad0, b0,
                                       W1, as1, ad1, b1, Wm, bm, wg, bg, out);
}

// round 6
// speedup vs baseline: 1.0800x; 1.0196x over previous
#include <cuda_runtime.h>

#define NN 52      // nodes
#define NE 832     // edges
#define E2 884     // edges + self loops
#define FD 256     // feature dim
#define NT 512     // threads per CTA
#define RS 56      // padded row stride of transposed tile

union F2U { float2 f; unsigned long long u; };

__device__ __forceinline__ unsigned long long pack2(float a, float b){
    F2U t; t.f = make_float2(a, b); return t.u;
}
__device__ __forceinline__ float2 unpack2(unsigned long long v){
    F2U t; t.u = v; return t.f;
}
// packed dual-fp32 FMA (sm_100+)
__device__ __forceinline__ void fma2(unsigned long long& d,
                                     unsigned long long a,
                                     unsigned long long b){
    asm("fma.rn.f32x2 %0, %1, %2, %0;" : "+l"(d) : "l"(a), "l"(b));
}
__device__ __forceinline__ float sigmoidf_(float x){
    return 1.f / (1.f + __expf(-x));
}

// shared memory accounting
constexpr int SM_WORDS = FD*RS + NN*FD + E2*2 + NN*5 + FD*5 + NT*2
                       + E2*2 + (NN+1) + NN;
constexpr int SMEM_BYTES = SM_WORDS * 4;

__global__ void __launch_bounds__(NT, 1)
gcab_kernel(const float* __restrict__ xg, const void* __restrict__ eig,
            const float* __restrict__ W0, const float* __restrict__ as0,
            const float* __restrict__ ad0, const float* __restrict__ b0,
            const float* __restrict__ W1, const float* __restrict__ as1,
            const float* __restrict__ ad1, const float* __restrict__ b1,
            const float* __restrict__ Wm, const float* __restrict__ bm,
            const float* __restrict__ wgp, const float* __restrict__ bgp,
            float* __restrict__ outg)
{
    extern __shared__ float sm[];
    float* sAT   = sm;                 // [256][56] transposed activations
    float* sB    = sAT + FD*RS;        // [52][256] xp (row-major)
    int2*  sEC   = (int2*)(sB + NN*FD);// [884] CSR-ordered {src, alpha_bits}
    float* sECf  = (float*)sEC;
    float* sAsrc = (float*)(sEC + E2); // [52]
    float* sAdst = sAsrc + NN;         // [52]
    float* sHmax = sAdst + NN;         // [52]
    float* sDinv = sHmax + NN;         // [52]
    float* sMno  = sDinv + NN;         // [52]
    float* sAs   = sMno + NN;          // [256]
    float* sAd   = sAs + FD;           // [256]
    float* sAvg  = sAd + FD;           // [256]
    float* sMx   = sAvg + FD;          // [256]
    float* sMch  = sMx + FD;           // [256]
    float* sPa   = sMch + FD;          // [512]
    float* sPm   = sPa + NT;           // [512]
    int*   sS    = (int*)(sPm + NT);   // [884]
    int*   sD    = sS + E2;            // [884]
    int*   sOff  = sD + E2;            // [53]
    int*   sCnt  = sOff + (NN+1);      // [52]
    __shared__ int sIs64;

    const int tid  = threadIdx.x;
    const int g    = blockIdx.x;
    const int lane = tid & 31, wrp = tid >> 5;

    // ------- detect edge_index dtype (int64 vs int32) -------
    if (tid == 0){
        const int* e32 = (const int*)eig;
        int flag = 1;
        #pragma unroll 1
        for (int i = 0; i < 32; i++){
            if (e32[2*i + 1] != 0){ flag = 0; break; }
        }
        sIs64 = flag;
    }

    // ---------------- load x transposed directly ----------------
    {
        const float* xr = xg + (size_t)g*NN*FD;
        for (int i = tid; i < NN*FD; i += NT){
            int r = i >> 8;
            int f = i & 255;
            sAT[f*RS + r] = xr[i];
        }
        if (tid < NN) sCnt[tid] = 0;
    }
    __syncthreads();

    // ---------------- load edges ----------------
    {
        const int is64 = sIs64;
        const long long* ei64 = (const long long*)eig + (size_t)g*2*NE;
        const int*       ei32 = (const int*)eig       + (size_t)g*2*NE;
        for (int e = tid; e < E2; e += NT){
            int s, d;
            if (e < NE){
                if (is64){ s = (int)ei64[e]; d = (int)ei64[NE + e]; }
                else     { s = ei32[e];      d = ei32[NE + e]; }
            } else {
                s = e - NE; d = e - NE;
            }
            sS[e] = s; sD[e] = d;
        }
    }
    __syncthreads();
    for (int e = tid; e < E2; e += NT) atomicAdd(&sCnt[sD[e]], 1);
    __syncthreads();
    if (tid == 0){
        int acc = 0;
        for (int i = 0; i < NN; i++){ sOff[i] = acc; acc += sCnt[i]; }
        sOff[NN] = acc;
    }
    __syncthreads();
    // deterministic CSR fill: 4 nodes per warp
    {
        const int nd0 = wrp, nd1 = wrp+16, nd2 = wrp+32, nd3 = wrp+48;
        int pos0 = sOff[nd0];
        int pos1 = sOff[nd1];
        int pos2 = sOff[nd2];
        int pos3 = (nd3 < NN) ? sOff[nd3] : 0;
        const unsigned lt = (1u << lane) - 1u;
        for (int base = 0; base < E2; base += 32){
            int e = base + lane;
            int d = -1, s = 0;
            if (e < E2){ d = sD[e]; s = sS[e]; }
            unsigned m0 = __ballot_sync(0xffffffffu, d == nd0);
            if (d == nd0) sEC[pos0 + __popc(m0 & lt)].x = s;
            pos0 += __popc(m0);
            unsigned m1 = __ballot_sync(0xffffffffu, d == nd1);
            if (d == nd1) sEC[pos1 + __popc(m1 & lt)].x = s;
            pos1 += __popc(m1);
            unsigned m2 = __ballot_sync(0xffffffffu, d == nd2);
            if (d == nd2) sEC[pos2 + __popc(m2 & lt)].x = s;
            pos2 += __popc(m2);
            unsigned m3 = __ballot_sync(0xffffffffu, d == nd3);
            if (d == nd3) sEC[pos3 + __popc(m3 & lt)].x = s;
            pos3 += __popc(m3);
        }
    }
    if (tid < NN) sDinv[tid] = rsqrtf((float)sCnt[tid]);
    __syncthreads();

    // GEMM thread mapping
    const int cg = tid & 127;        // column pair: cols 2cg, 2cg+1
    const int rg = (tid >> 7) & 1;   // rows rg*26 .. +26 (13 pairs)
    const int kh = tid >> 8;         // k half

    // ---------------- two GAT rounds ----------------
    for (int rnd = 0; rnd < 2; rnd++){
        const float* W  = rnd ? W1  : W0;
        const float* av = rnd ? as1 : as0;
        const float* dv = rnd ? ad1 : ad0;
        const float* bb = rnd ? b1  : b0;
        for (int i = tid; i < FD; i += NT){ sAs[i] = av[i]; sAd[i] = dv[i]; }

        // GEMM: sB[52][256] = A[52][256] @ W[256][256]
        // W double-buffered 8-k register blocks (distance >= 8 k's)
        {
            unsigned long long acc[13][2];
#pragma unroll
            for (int i = 0; i < 13; i++){ acc[i][0] = 0ull; acc[i][1] = 0ull; }
            const float* wbase = W + (size_t)(kh*128)*FD + 2*cg;
            const float* xbase = sAT + (kh*128)*RS + rg*26;

            float2 wA[8], wB[8];
#pragma unroll
            for (int j = 0; j < 8; j++)
                wA[j] = *reinterpret_cast<const float2*>(wbase + (size_t)j*FD);

#pragma unroll 1
            for (int kb = 0; kb < 128; kb += 16){
                // prefetch block B: k = kb+8 .. kb+15
#pragma unroll
                for (int j = 0; j < 8; j++)
                    wB[j] = *reinterpret_cast<const float2*>(wbase + (size_t)(kb+8+j)*FD);
                // process block A: k = kb .. kb+7
#pragma unroll
                for (int j = 0; j < 8; j++){
                    unsigned long long w0 = pack2(wA[j].x, wA[j].x);
                    unsigned long long w1 = pack2(wA[j].y, wA[j].y);
                    const float2* xr = reinterpret_cast<const float2*>(xbase + (size_t)(kb+j)*RS);
#pragma unroll
                    for (int i = 0; i < 13; i++){
                        F2U xv; xv.f = xr[i];
                        fma2(acc[i][0], xv.u, w0);
                        fma2(acc[i][1], xv.u, w1);
                    }
                }
                // prefetch block A: k = kb+16 .. kb+23 (clamped)
                {
                    int kn = (kb + 16 < 128) ? (kb + 16) : 0;
#pragma unroll
                    for (int j = 0; j < 8; j++)
                        wA[j] = *reinterpret_cast<const float2*>(wbase + (size_t)(kn+j)*FD);
                }
                // process block B: k = kb+8 .. kb+15
#pragma unroll
                for (int j = 0; j < 8; j++){
                    unsigned long long w0 = pack2(wB[j].x, wB[j].x);
                    unsigned long long w1 = pack2(wB[j].y, wB[j].y);
                    const float2* xr = reinterpret_cast<const float2*>(xbase + (size_t)(kb+8+j)*RS);
#pragma unroll
                    for (int i = 0; i < 13; i++){
                        F2U xv; xv.f = xr[i];
                        fma2(acc[i][0], xv.u, w0);
                        fma2(acc[i][1], xv.u, w1);
                    }
                }
            }
            // k-half 0 writes, k-half 1 accumulates
            if (kh == 0){
#pragma unroll
                for (int i = 0; i < 13; i++){
                    float2 c0 = unpack2(acc[i][0]);
                    float2 c1 = unpack2(acc[i][1]);
                    int r0 = rg*26 + 2*i;
                    reinterpret_cast<float2*>(sB + r0*FD)[cg]     = make_float2(c0.x, c1.x);
                    reinterpret_cast<float2*>(sB + (r0+1)*FD)[cg] = make_float2(c0.y, c1.y);
                }
            }
            __syncthreads();
            if (kh == 1){
#pragma unroll
                for (int i = 0; i < 13; i++){
                    float2 c0 = unpack2(acc[i][0]);
                    float2 c1 = unpack2(acc[i][1]);
                    int r0 = rg*26 + 2*i;
                    float2* p0 = &reinterpret_cast<float2*>(sB + r0*FD)[cg];
                    float2* p1 = &reinterpret_cast<float2*>(sB + (r0+1)*FD)[cg];
                    float2 o0 = *p0, o1 = *p1;
                    *p0 = make_float2(o0.x + c0.x, o0.y + c1.x);
                    *p1 = make_float2(o1.x + c0.y, o1.y + c1.y);
                }
            }
            __syncthreads();
        }

        // asrc/adst per row: warp-per-row reductions
        for (int r = wrp; r < NN; r += 16){
            float sa = 0.f, sd = 0.f;
#pragma unroll
            for (int t = 0; t < 8; t++){
                float v = sB[r*FD + lane + 32*t];
                sa += v * sAs[lane + 32*t];
                sd += v * sAd[lane + 32*t];
            }
#pragma unroll
            for (int o = 16; o; o >>= 1){
                sa += __shfl_down_sync(0xffffffffu, sa, o);
                sd += __shfl_down_sync(0xffffffffu, sd, o);
            }
            if (lane == 0){ sAsrc[r] = sa; sAdst[r] = sd; }
        }
        __syncthreads();

        // fused logits + per-dest softmax on CSR slots: warp per node
        for (int nd = wrp; nd < NN; nd += 16){
            int beg = sOff[nd], end = sOff[nd+1];
            float adn = sAdst[nd];
            float m = -3.0e38f;
            for (int t = beg + lane; t < end; t += 32){
                int src = sEC[t].x;
                float el = sAsrc[src] + adn;
                el = el > 0.f ? el : 0.2f * el;
                sECf[2*t+1] = el;
                m = fmaxf(m, el);
            }
#pragma unroll
            for (int o = 16; o; o >>= 1)
                m = fmaxf(m, __shfl_xor_sync(0xffffffffu, m, o));
            float s = 0.f;
            for (int t = beg + lane; t < end; t += 32){
                float w = __expf(sECf[2*t+1] - m);
                sECf[2*t+1] = w;
                s += w;
            }
#pragma unroll
            for (int o = 16; o; o >>= 1)
                s += __shfl_xor_sync(0xffffffffu, s, o);
            float inv = 1.f / s;
            for (int t = beg + lane; t < end; t += 32)
                sECf[2*t+1] *= inv;
        }
        __syncthreads();

        // aggregation: 128 column-pairs x 4 row quarters; writes transposed sAT
        {
            const int p  = tid & 127;
            const int q  = tid >> 7;
            const float2* sB2 = reinterpret_cast<const float2*>(sB);
            float2 bbv = reinterpret_cast<const float2*>(bb)[p];
            for (int dd = q*13; dd < q*13 + 13; dd++){
                int beg = sOff[dd], end = sOff[dd+1];
                unsigned long long acc = 0ull;
                for (int t = beg; t < end; t++){
                    int2 v = sEC[t];
                    float al = __int_as_float(v.y);
                    F2U xv; xv.f = sB2[v.x*(FD/2) + p];
                    fma2(acc, xv.u, pack2(al, al));
                }
                float2 r = unpack2(acc);
                float v0 = r.x + bbv.x;
                float v1 = r.y + bbv.y;
                float* a0 = &sAT[(2*p  )*RS + dd];
                float* a1 = &sAT[(2*p+1)*RS + dd];
                if (rnd == 1){
                    v0 = fmaxf(v0 + *a0, 0.f);
                    v1 = fmaxf(v1 + *a1, 0.f);
                }
                *a0 = v0;
                *a1 = v1;
            }
        }
        __syncthreads();
    }

    // ---------------- channel attention ----------------
    {
        const int j = tid & 255, half = tid >> 8;
        float s = 0.f, m = -3.0e38f;
        for (int r = half*26; r < half*26 + 26; r++){
            float v = sAT[j*RS + r];
            s += v; m = fmaxf(m, v);
        }
        sPa[tid] = s; sPm[tid] = m;
    }
    __syncthreads();
    if (tid < FD){
        sAvg[tid] = (sPa[tid] + sPa[tid + 256]) * (1.f/52.f);
        sMx[tid]  = fmaxf(sPm[tid], sPm[tid + 256]);
    }
    __syncthreads();
    {
        const int j = tid & 255, half = tid >> 8;
        float aA = 0.f, aM = 0.f;
        const float* wc = Wm + j;
#pragma unroll 4
        for (int k = half*128; k < half*128 + 128; k++){
            float w = wc[k*FD];
            aA += sAvg[k]*w;
            aM += sMx[k]*w;
        }
        sPa[tid] = aA; sPm[tid] = aM;
    }
    __syncthreads();
    if (tid < FD){
        float aA = sPa[tid] + sPa[tid + 256];
        float aM = sPm[tid] + sPm[tid + 256];
        float bj = bm[tid];
        sMch[tid] = sigmoidf_(fmaxf(aA + bj, 0.f) + fmaxf(aM + bj, 0.f));
    }
    __syncthreads();

    // ---------------- node attention ----------------
    for (int r = wrp; r < NN; r += 16){
        float mx = -3.0e38f;
#pragma unroll
        for (int t = 0; t < 8; t++){
            int f = lane + 32*t;
            mx = fmaxf(mx, sAT[f*RS + r] * sMch[f]);
        }
#pragma unroll
        for (int o = 16; o; o >>= 1)
            mx = fmaxf(mx, __shfl_down_sync(0xffffffffu, mx, o));
        if (lane == 0) sHmax[r] = mx;
    }
    __syncthreads();
    if (tid < NN){
        float s = 0.f;
        int beg = sOff[tid], end = sOff[tid+1];
        for (int t = beg; t < end; t++){
            int ss = sEC[t].x;
            s += sDinv[ss] * sHmax[ss];
        }
        float aggv = sDinv[tid] * s * wgp[0] + bgp[0];
        sMno[tid] = sigmoidf_(aggv);
    }
    __syncthreads();

    // ---------------- final write (mch * mno folded) ----------------
    {
        float* op = outg + (size_t)g*NN*FD;
        for (int i = tid; i < NN*FD; i += NT){
            int r = i >> 8, f = i & 255;
            op[i] = sAT[f*RS + r] * sMch[f] * sMno[r];
        }
    }
}

extern "C" void kernel_launch(void* const* d_in, const int* in_sizes, int n_in,
                              void* d_out, int out_size)
{
    const float* x   = (const float*)d_in[0];
    const void*  ei  = d_in[1];
    const float* W0  = (const float*)d_in[2];
    const float* as0 = (const float*)d_in[3];
    const float* ad0 = (const float*)d_in[4];
    const float* b0  = (const float*)d_in[5];
    const float* W1  = (const float*)d_in[6];
    const float* as1 = (const float*)d_in[7];
    const float* ad1 = (const float*)d_in[8];
    const float* b1  = (const float*)d_in[9];
    const float* Wm  = (const float*)d_in[10];
    const float* bm  = (const float*)d_in[11];
    const float* wg  = (const float*)d_in[12];
    const float* bg  = (const float*)d_in[13];
    float* out = (float*)d_out;

    int B = in_sizes[0] / (NN*FD);

    cudaFuncSetAttribute(gcab_kernel,
                         cudaFuncAttributeMaxDynamicSharedMemorySize,
                         SMEM_BYTES);
    gcab_kernel<<<B, NT, SMEM_BYTES>>>(x, ei, W0, as0, ad0, b0,
                                       W1, as1, ad1, b1, Wm, bm, wg, bg, out);
}

// round 7
// speedup vs baseline: 1.2808x; 1.1859x over previous
#include <cuda_runtime.h>

#define NN 52      // nodes
#define NE 832     // edges
#define E2 884     // edges + self loops
#define FD 256     // feature dim
#define NT 256     // threads per CTA (2 CTAs/SM)

union F2U { float2 f; unsigned long long u; };

__device__ __forceinline__ unsigned long long pack2(float a, float b){
    F2U t; t.f = make_float2(a, b); return t.u;
}
__device__ __forceinline__ float2 unpack2(unsigned long long v){
    F2U t; t.u = v; return t.f;
}
// packed dual-fp32 FMA (sm_100+)
__device__ __forceinline__ void fma2(unsigned long long& d,
                                     unsigned long long a,
                                     unsigned long long b){
    asm("fma.rn.f32x2 %0, %1, %2, %0;" : "+l"(d) : "l"(a), "l"(b));
}
__device__ __forceinline__ float sigmoidf_(float x){
    return 1.f / (1.f + __expf(-x));
}

// paired-row address: element (r, k) of the activation tile
__device__ __forceinline__ int paddr(int r, int k){
    return (r >> 1)*2*FD + 2*k + (r & 1);
}

// shared memory: sA(paired) + sB + alpha + src16 + as/ad + small + off
constexpr int SM_WORDS = NN*FD + NN*FD + E2 + (E2+1)/2 + FD*2 + NN*5 + (NN+1);
constexpr int SMEM_BYTES = SM_WORDS * 4;

__global__ void __launch_bounds__(NT, 2)
gcab_kernel(const float* __restrict__ xg, const void* __restrict__ eig,
            const float* __restrict__ W0, const float* __restrict__ as0,
            const float* __restrict__ ad0, const float* __restrict__ b0,
            const float* __restrict__ W1, const float* __restrict__ as1,
            const float* __restrict__ ad1, const float* __restrict__ b1,
            const float* __restrict__ Wm, const float* __restrict__ bm,
            const float* __restrict__ wgp, const float* __restrict__ bgp,
            float* __restrict__ outg)
{
    extern __shared__ float sm[];
    float* sA    = sm;                 // [26 pairs][512] paired-row activations
    float* sB    = sA + NN*FD;         // [52][256] xp row-major (+ overlays)
    float* sAlpha= sB + NN*FD;         // [884] edge alpha
    short* sSrc  = (short*)(sAlpha + E2);        // [884] src (int16)
    float* sAs   = sAlpha + E2 + (E2+1)/2;       // [256]
    float* sAd   = sAs + FD;           // [256]
    float* sAsrc = sAd + FD;           // [52]
    float* sAdst = sAsrc + NN;         // [52]
    float* sHmax = sAdst + NN;         // [52]
    float* sDinv = sHmax + NN;         // [52]
    float* sMno  = sDinv + NN;         // [52]
    int*   sOff  = (int*)(sMno + NN);  // [53]
    // setup-phase overlays inside sB
    int*   sS    = (int*)sB;           // [884]
    int*   sD    = sS + E2;            // [884]
    int*   sCnt  = sD + E2;            // [52]
    // epilogue-phase overlays inside sB
    float* sAvg  = sB;                 // [256]
    float* sMx   = sB + FD;            // [256]
    float* sMch  = sB + 2*FD;          // [256]
    __shared__ int sIs64;

    const int tid  = threadIdx.x;
    const int g    = blockIdx.x;
    const int lane = tid & 31, wrp = tid >> 5;

    // ------- detect edge_index dtype (int64 vs int32) -------
    if (tid == 0){
        const int* e32 = (const int*)eig;
        int flag = 1;
        #pragma unroll 1
        for (int i = 0; i < 32; i++){
            if (e32[2*i + 1] != 0){ flag = 0; break; }
        }
        sIs64 = flag;
    }

    // ---------------- load x into paired layout ----------------
    {
        const float* xr = xg + (size_t)g*NN*FD;
        for (int i = tid; i < NN*FD; i += NT){
            int r = i >> 8;
            int f = i & 255;
            sA[paddr(r, f)] = xr[i];
        }
        if (tid < NN) sCnt[tid] = 0;
    }
    __syncthreads();

    // ---------------- load edges (into sB overlay) ----------------
    {
        const int is64 = sIs64;
        const long long* ei64 = (const long long*)eig + (size_t)g*2*NE;
        const int*       ei32 = (const int*)eig       + (size_t)g*2*NE;
        for (int e = tid; e < E2; e += NT){
            int s, d;
            if (e < NE){
                if (is64){ s = (int)ei64[e]; d = (int)ei64[NE + e]; }
                else     { s = ei32[e];      d = ei32[NE + e]; }
            } else {
                s = e - NE; d = e - NE;
            }
            sS[e] = s; sD[e] = d;
        }
    }
    __syncthreads();
    for (int e = tid; e < E2; e += NT) atomicAdd(&sCnt[sD[e]], 1);
    __syncthreads();
    if (tid == 0){
        int acc = 0;
        for (int i = 0; i < NN; i++){ sOff[i] = acc; acc += sCnt[i]; }
        sOff[NN] = acc;
    }
    if (tid >= 32 && tid < 32 + NN) sDinv[tid-32] = rsqrtf((float)sCnt[tid-32]);
    __syncthreads();
    // deterministic CSR fill: 7 nodes per warp (8 warps), writes int16 src
    {
        int nds[7], poss[7];
#pragma unroll
        for (int j = 0; j < 7; j++){
            nds[j]  = wrp + 8*j;
            poss[j] = (nds[j] < NN) ? sOff[nds[j]] : 0;
        }
        const unsigned lt = (1u << lane) - 1u;
        for (int base = 0; base < E2; base += 32){
            int e = base + lane;
            int d = -1, s = 0;
            if (e < E2){ d = sD[e]; s = sS[e]; }
#pragma unroll
            for (int j = 0; j < 7; j++){
                unsigned m = __ballot_sync(0xffffffffu, d == nds[j]);
                if (d == nds[j]) sSrc[poss[j] + __popc(m & lt)] = (short)s;
                poss[j] += __popc(m);
            }
        }
    }
    __syncthreads();

    // GEMM thread mapping: 128 col-pairs x 2 row-halves, full k
    const int cg = tid & 127;        // cols 2cg, 2cg+1
    const int rg = tid >> 7;         // pairs rg*13 .. +13 (rows rg*26..+26)

    // ---------------- two GAT rounds ----------------
    for (int rnd = 0; rnd < 2; rnd++){
        const float* W  = rnd ? W1  : W0;
        const float* av = rnd ? as1 : as0;
        const float* dv = rnd ? ad1 : ad0;
        const float* bb = rnd ? b1  : b0;
        for (int i = tid; i < FD; i += NT){ sAs[i] = av[i]; sAd[i] = dv[i]; }
        __syncthreads();   // sB (epilogue overlay / old xp) reuse barrier

        // GEMM: sB[52][256] = A[52][256] @ W[256][256]
        {
            unsigned long long acc[13][2];
#pragma unroll
            for (int i = 0; i < 13; i++){ acc[i][0] = 0ull; acc[i][1] = 0ull; }
            const float* wbase = W + 2*cg;
            const float* xbase = sA + rg*13*512;

            float2 wA[8], wB[8];
#pragma unroll
            for (int j = 0; j < 8; j++)
                wA[j] = *reinterpret_cast<const float2*>(wbase + (size_t)j*FD);

#pragma unroll 1
            for (int kb = 0; kb < 256; kb += 16){
#pragma unroll
                for (int j = 0; j < 8; j++)
                    wB[j] = *reinterpret_cast<const float2*>(wbase + (size_t)(kb+8+j)*FD);
#pragma unroll
                for (int j = 0; j < 8; j++){
                    unsigned long long w0 = pack2(wA[j].x, wA[j].x);
                    unsigned long long w1 = pack2(wA[j].y, wA[j].y);
                    const float* xk = xbase + 2*(kb+j);
#pragma unroll
                    for (int i = 0; i < 13; i++){
                        F2U xv; xv.f = *reinterpret_cast<const float2*>(xk + i*512);
                        fma2(acc[i][0], xv.u, w0);
                        fma2(acc[i][1], xv.u, w1);
                    }
                }
                {
                    int kn = (kb + 16 < 256) ? (kb + 16) : 0;
#pragma unroll
                    for (int j = 0; j < 8; j++)
                        wA[j] = *reinterpret_cast<const float2*>(wbase + (size_t)(kn+j)*FD);
                }
#pragma unroll
                for (int j = 0; j < 8; j++){
                    unsigned long long w0 = pack2(wB[j].x, wB[j].x);
                    unsigned long long w1 = pack2(wB[j].y, wB[j].y);
                    const float* xk = xbase + 2*(kb+8+j);
#pragma unroll
                    for (int i = 0; i < 13; i++){
                        F2U xv; xv.f = *reinterpret_cast<const float2*>(xk + i*512);
                        fma2(acc[i][0], xv.u, w0);
                        fma2(acc[i][1], xv.u, w1);
                    }
                }
            }
#pragma unroll
            for (int i = 0; i < 13; i++){
                float2 c0 = unpack2(acc[i][0]);   // col 2cg, rows (2i, 2i+1)
                float2 c1 = unpack2(acc[i][1]);   // col 2cg+1
                int r0 = rg*26 + 2*i;
                reinterpret_cast<float2*>(sB + r0*FD)[cg]     = make_float2(c0.x, c1.x);
                reinterpret_cast<float2*>(sB + (r0+1)*FD)[cg] = make_float2(c0.y, c1.y);
            }
        }
        __syncthreads();

        // asrc/adst per row: warp-per-row (8 warps)
        for (int r = wrp; r < NN; r += 8){
            float sa = 0.f, sd = 0.f;
#pragma unroll
            for (int t = 0; t < 8; t++){
                float v = sB[r*FD + lane + 32*t];
                sa += v * sAs[lane + 32*t];
                sd += v * sAd[lane + 32*t];
            }
#pragma unroll
            for (int o = 16; o; o >>= 1){
                sa += __shfl_down_sync(0xffffffffu, sa, o);
                sd += __shfl_down_sync(0xffffffffu, sd, o);
            }
            if (lane == 0){ sAsrc[r] = sa; sAdst[r] = sd; }
        }
        __syncthreads();

        // fused logits + per-dest softmax: warp per node
        for (int nd = wrp; nd < NN; nd += 8){
            int beg = sOff[nd], end = sOff[nd+1];
            float adn = sAdst[nd];
            float m = -3.0e38f;
            for (int t = beg + lane; t < end; t += 32){
                int src = sSrc[t];
                float el = sAsrc[src] + adn;
                el = el > 0.f ? el : 0.2f * el;
                sAlpha[t] = el;
                m = fmaxf(m, el);
            }
#pragma unroll
            for (int o = 16; o; o >>= 1)
                m = fmaxf(m, __shfl_xor_sync(0xffffffffu, m, o));
            float s = 0.f;
            for (int t = beg + lane; t < end; t += 32){
                float w = __expf(sAlpha[t] - m);
                sAlpha[t] = w;
                s += w;
            }
#pragma unroll
            for (int o = 16; o; o >>= 1)
                s += __shfl_xor_sync(0xffffffffu, s, o);
            float inv = 1.f / s;
            for (int t = beg + lane; t < end; t += 32)
                sAlpha[t] *= inv;
        }
        __syncthreads();

        // aggregation: 128 col-pairs x 2 row halves; writes paired sA
        {
            const int p = tid & 127;
            const int q = tid >> 7;
            const float2* sB2 = reinterpret_cast<const float2*>(sB);
            float2 bbv = reinterpret_cast<const float2*>(bb)[p];
            for (int dd = q*26; dd < q*26 + 26; dd++){
                int beg = sOff[dd], end = sOff[dd+1];
                unsigned long long acc = 0ull;
                for (int t = beg; t < end; t++){
                    int src = sSrc[t];
                    float al = sAlpha[t];
                    F2U xv; xv.f = sB2[src*(FD/2) + p];
                    fma2(acc, xv.u, pack2(al, al));
                }
                float2 r = unpack2(acc);
                float v0 = r.x + bbv.x;
                float v1 = r.y + bbv.y;
                int a0 = (dd >> 1)*512 + 4*p + (dd & 1);
                if (rnd == 1){
                    v0 = fmaxf(v0 + sA[a0],     0.f);
                    v1 = fmaxf(v1 + sA[a0 + 2], 0.f);
                }
                sA[a0]     = v0;
                sA[a0 + 2] = v1;
            }
        }
        __syncthreads();
    }

    // ---------------- channel attention (thread = column) ----------------
    {
        const int j = tid;
        float s = 0.f, m = -3.0e38f;
#pragma unroll 4
        for (int r = 0; r < NN; r++){
            float v = sA[paddr(r, j)];
            s += v; m = fmaxf(m, v);
        }
        sAvg[j] = s * (1.f/52.f);
        sMx[j]  = m;
    }
    __syncthreads();
    {
        const int j = tid;
        float aA = 0.f, aM = 0.f;
        const float* wc = Wm + j;
#pragma unroll 4
        for (int k = 0; k < FD; k++){
            float w = wc[k*FD];
            aA += sAvg[k]*w;
            aM += sMx[k]*w;
        }
        float bj = bm[j];
        float mval = sigmoidf_(fmaxf(aA + bj, 0.f) + fmaxf(aM + bj, 0.f));
        __syncthreads();     // sAvg/sMx reads complete before sMch write zone reuse
        sMch[j] = mval;
    }
    __syncthreads();

    // ---------------- node attention ----------------
    for (int r = wrp; r < NN; r += 8){
        float mx = -3.0e38f;
#pragma unroll
        for (int t = 0; t < 8; t++){
            int f = lane + 32*t;
            mx = fmaxf(mx, sA[paddr(r, f)] * sMch[f]);
        }
#pragma unroll
        for (int o = 16; o; o >>= 1)
            mx = fmaxf(mx, __shfl_down_sync(0xffffffffu, mx, o));
        if (lane == 0) sHmax[r] = mx;
    }
    __syncthreads();
    if (tid < NN){
        float s = 0.f;
        int beg = sOff[tid], end = sOff[tid+1];
        for (int t = beg; t < end; t++){
            int ss = sSrc[t];
            s += sDinv[ss] * sHmax[ss];
        }
        float aggv = sDinv[tid] * s * wgp[0] + bgp[0];
        sMno[tid] = sigmoidf_(aggv);
    }
    __syncthreads();

    // ---------------- final write ----------------
    {
        float* op = outg + (size_t)g*NN*FD;
        for (int i = tid; i < NN*FD; i += NT){
            int r = i >> 8, f = i & 255;
            op[i] = sA[paddr(r, f)] * sMch[f] * sMno[r];
        }
    }
}

extern "C" void kernel_launch(void* const* d_in, const int* in_sizes, int n_in,
                              void* d_out, int out_size)
{
    const float* x   = (const float*)d_in[0];
    const void*  ei  = d_in[1];
    const float* W0  = (const float*)d_in[2];
    const float* as0 = (const float*)d_in[3];
    const float* ad0 = (const float*)d_in[4];
    const float* b0  = (const float*)d_in[5];
    const float* W1  = (const float*)d_in[6];
    const float* as1 = (const float*)d_in[7];
    const float* ad1 = (const float*)d_in[8];
    const float* b1  = (const float*)d_in[9];
    const float* Wm  = (const float*)d_in[10];
    const float* bm  = (const float*)d_in[11];
    const float* wg  = (const float*)d_in[12];
    const float* bg  = (const float*)d_in[13];
    float* out = (float*)d_out;

    int B = in_sizes[0] / (NN*FD);

    cudaFuncSetAttribute(gcab_kernel,
                         cudaFuncAttributeMaxDynamicSharedMemorySize,
                         SMEM_BYTES);
    gcab_kernel<<<B, NT, SMEM_BYTES>>>(x, ei, W0, as0, ad0, b0,
                                       W1, as1, ad1, b1, Wm, bm, wg, bg, out);
}

// round 8
// speedup vs baseline: 1.2893x; 1.0067x over previous
#include <cuda_runtime.h>

#define NN 52      // nodes
#define NE 832     // edges
#define E2 884     // edges + self loops
#define FD 256     // feature dim
#define NT 256     // threads per CTA (2 CTAs/SM)

union F2U { float2 f; unsigned long long u; };

__device__ __forceinline__ unsigned long long pack2(float a, float b){
    F2U t; t.f = make_float2(a, b); return t.u;
}
__device__ __forceinline__ float2 unpack2(unsigned long long v){
    F2U t; t.u = v; return t.f;
}
// packed dual-fp32 FMA (sm_100+)
__device__ __forceinline__ void fma2(unsigned long long& d,
                                     unsigned long long a,
                                     unsigned long long b){
    asm("fma.rn.f32x2 %0, %1, %2, %0;" : "+l"(d) : "l"(a), "l"(b));
}
__device__ __forceinline__ float sigmoidf_(float x){
    return 1.f / (1.f + __expf(-x));
}

// paired-row address: element (r, k) of the activation tile
__device__ __forceinline__ int paddr(int r, int k){
    return (r >> 1)*2*FD + 2*k + (r & 1);
}

// shared memory: sA(paired) + sB + alpha + src16 + as/ad + small + off
constexpr int SM_WORDS = NN*FD + NN*FD + E2 + (E2+1)/2 + FD*2 + NN*5 + (NN+1);
constexpr int SMEM_BYTES = SM_WORDS * 4;

__global__ void __launch_bounds__(NT, 2)
gcab_kernel(const float* __restrict__ xg, const void* __restrict__ eig,
            const float* __restrict__ W0, const float* __restrict__ as0,
            const float* __restrict__ ad0, const float* __restrict__ b0,
            const float* __restrict__ W1, const float* __restrict__ as1,
            const float* __restrict__ ad1, const float* __restrict__ b1,
            const float* __restrict__ Wm, const float* __restrict__ bm,
            const float* __restrict__ wgp, const float* __restrict__ bgp,
            float* __restrict__ outg)
{
    extern __shared__ float sm[];
    float* sA    = sm;                 // [26 pairs][512] paired-row activations
    float* sB    = sA + NN*FD;         // [52][256] xp row-major (+ overlays)
    float* sAlpha= sB + NN*FD;         // [884] edge alpha
    short* sSrc  = (short*)(sAlpha + E2);        // [884] src (int16)
    float* sAs   = sAlpha + E2 + (E2+1)/2;       // [256]
    float* sAd   = sAs + FD;           // [256]
    float* sAsrc = sAd + FD;           // [52]
    float* sAdst = sAsrc + NN;         // [52]
    float* sHmax = sAdst + NN;         // [52]
    float* sDinv = sHmax + NN;         // [52]
    float* sMno  = sDinv + NN;         // [52]
    int*   sOff  = (int*)(sMno + NN);  // [53]
    // setup-phase overlays inside sB
    int*   sS    = (int*)sB;           // [884]
    int*   sD    = sS + E2;            // [884]
    int*   sCnt  = sD + E2;            // [52]
    // epilogue-phase overlays inside sB
    float* sAvg  = sB;                 // [256]
    float* sMx   = sB + FD;            // [256]
    float* sMch  = sB + 2*FD;          // [256]
    __shared__ int sIs64;

    const int tid  = threadIdx.x;
    const int g    = blockIdx.x;
    const int lane = tid & 31, wrp = tid >> 5;

    // ------- detect edge_index dtype (int64 vs int32) -------
    if (tid == 0){
        const int* e32 = (const int*)eig;
        int flag = 1;
        #pragma unroll 1
        for (int i = 0; i < 32; i++){
            if (e32[2*i + 1] != 0){ flag = 0; break; }
        }
        sIs64 = flag;
    }

    // ---------------- load x into paired layout ----------------
    {
        const float* xr = xg + (size_t)g*NN*FD;
        for (int i = tid; i < NN*FD; i += NT){
            int r = i >> 8;
            int f = i & 255;
            sA[paddr(r, f)] = xr[i];
        }
        if (tid < NN) sCnt[tid] = 0;
    }
    __syncthreads();

    // ---------------- load edges (into sB overlay) ----------------
    {
        const int is64 = sIs64;
        const long long* ei64 = (const long long*)eig + (size_t)g*2*NE;
        const int*       ei32 = (const int*)eig       + (size_t)g*2*NE;
        for (int e = tid; e < E2; e += NT){
            int s, d;
            if (e < NE){
                if (is64){ s = (int)ei64[e]; d = (int)ei64[NE + e]; }
                else     { s = ei32[e];      d = ei32[NE + e]; }
            } else {
                s = e - NE; d = e - NE;
            }
            sS[e] = s; sD[e] = d;
        }
    }
    __syncthreads();
    for (int e = tid; e < E2; e += NT) atomicAdd(&sCnt[sD[e]], 1);
    __syncthreads();
    if (tid == 0){
        int acc = 0;
        for (int i = 0; i < NN; i++){ sOff[i] = acc; acc += sCnt[i]; }
        sOff[NN] = acc;
    }
    if (tid >= 32 && tid < 32 + NN) sDinv[tid-32] = rsqrtf((float)sCnt[tid-32]);
    __syncthreads();
    // deterministic CSR fill: 7 nodes per warp (8 warps), writes int16 src
    {
        int nds[7], poss[7];
#pragma unroll
        for (int j = 0; j < 7; j++){
            nds[j]  = wrp + 8*j;
            poss[j] = (nds[j] < NN) ? sOff[nds[j]] : 0;
        }
        const unsigned lt = (1u << lane) - 1u;
        for (int base = 0; base < E2; base += 32){
            int e = base + lane;
            int d = -1, s = 0;
            if (e < E2){ d = sD[e]; s = sS[e]; }
#pragma unroll
            for (int j = 0; j < 7; j++){
                unsigned m = __ballot_sync(0xffffffffu, d == nds[j]);
                if (d == nds[j]) sSrc[poss[j] + __popc(m & lt)] = (short)s;
                poss[j] += __popc(m);
            }
        }
    }
    __syncthreads();

    // GEMM thread mapping: 128 col-pairs x 2 row-halves, full k
    const int cg = tid & 127;        // cols 2cg, 2cg+1
    const int rg = tid >> 7;         // pairs rg*13 .. +13 (rows rg*26..+26)

    // ---------------- two GAT rounds ----------------
    for (int rnd = 0; rnd < 2; rnd++){
        const float* W  = rnd ? W1  : W0;
        const float* av = rnd ? as1 : as0;
        const float* dv = rnd ? ad1 : ad0;
        const float* bb = rnd ? b1  : b0;
        for (int i = tid; i < FD; i += NT){ sAs[i] = av[i]; sAd[i] = dv[i]; }
        __syncthreads();   // sB (epilogue overlay / old xp) reuse barrier

        // GEMM: sB[52][256] = A[52][256] @ W[256][256]
        // x loaded as LDS.128 k-pairs (paired layout interleaves k, k+1)
        {
            unsigned long long acc[13][2];
#pragma unroll
            for (int i = 0; i < 13; i++){ acc[i][0] = 0ull; acc[i][1] = 0ull; }
            const float* wbase = W + 2*cg;
            const float* xbase = sA + rg*13*512;

            float2 wA[8], wB[8];
#pragma unroll
            for (int j = 0; j < 8; j++)
                wA[j] = *reinterpret_cast<const float2*>(wbase + (size_t)j*FD);

#pragma unroll 1
            for (int kb = 0; kb < 256; kb += 16){
                // prefetch W block B: k = kb+8 .. kb+15
#pragma unroll
                for (int j = 0; j < 8; j++)
                    wB[j] = *reinterpret_cast<const float2*>(wbase + (size_t)(kb+8+j)*FD);
                // process block A: k-pairs (kb+2jp, kb+2jp+1)
#pragma unroll
                for (int jp = 0; jp < 4; jp++){
                    unsigned long long w00 = pack2(wA[2*jp  ].x, wA[2*jp  ].x);
                    unsigned long long w01 = pack2(wA[2*jp  ].y, wA[2*jp  ].y);
                    unsigned long long w10 = pack2(wA[2*jp+1].x, wA[2*jp+1].x);
                    unsigned long long w11 = pack2(wA[2*jp+1].y, wA[2*jp+1].y);
                    const float4* xq = reinterpret_cast<const float4*>(xbase + 2*(kb + 2*jp));
#pragma unroll
                    for (int i = 0; i < 13; i++){
                        float4 xv = xq[i*128];           // i*512 floats
                        F2U lo; lo.f = make_float2(xv.x, xv.y);
                        F2U hi; hi.f = make_float2(xv.z, xv.w);
                        fma2(acc[i][0], lo.u, w00);
                        fma2(acc[i][1], lo.u, w01);
                        fma2(acc[i][0], hi.u, w10);
                        fma2(acc[i][1], hi.u, w11);
                    }
                }
                // prefetch W block A: k = kb+16 .. kb+23 (clamped)
                {
                    int kn = (kb + 16 < 256) ? (kb + 16) : 0;
#pragma unroll
                    for (int j = 0; j < 8; j++)
                        wA[j] = *reinterpret_cast<const float2*>(wbase + (size_t)(kn+j)*FD);
                }
                // process block B: k-pairs (kb+8+2jp, kb+9+2jp)
#pragma unroll
                for (int jp = 0; jp < 4; jp++){
                    unsigned long long w00 = pack2(wB[2*jp  ].x, wB[2*jp  ].x);
                    unsigned long long w01 = pack2(wB[2*jp  ].y, wB[2*jp  ].y);
                    unsigned long long w10 = pack2(wB[2*jp+1].x, wB[2*jp+1].x);
                    unsigned long long w11 = pack2(wB[2*jp+1].y, wB[2*jp+1].y);
                    const float4* xq = reinterpret_cast<const float4*>(xbase + 2*(kb + 8 + 2*jp));
#pragma unroll
                    for (int i = 0; i < 13; i++){
                        float4 xv = xq[i*128];
                        F2U lo; lo.f = make_float2(xv.x, xv.y);
                        F2U hi; hi.f = make_float2(xv.z, xv.w);
                        fma2(acc[i][0], lo.u, w00);
                        fma2(acc[i][1], lo.u, w01);
                        fma2(acc[i][0], hi.u, w10);
                        fma2(acc[i][1], hi.u, w11);
                    }
                }
            }
#pragma unroll
            for (int i = 0; i < 13; i++){
                float2 c0 = unpack2(acc[i][0]);   // col 2cg, rows (2i, 2i+1)
                float2 c1 = unpack2(acc[i][1]);   // col 2cg+1
                int r0 = rg*26 + 2*i;
                reinterpret_cast<float2*>(sB + r0*FD)[cg]     = make_float2(c0.x, c1.x);
                reinterpret_cast<float2*>(sB + (r0+1)*FD)[cg] = make_float2(c0.y, c1.y);
            }
        }
        __syncthreads();

        // asrc/adst per row: warp-per-row (8 warps)
        for (int r = wrp; r < NN; r += 8){
            float sa = 0.f, sd = 0.f;
#pragma unroll
            for (int t = 0; t < 8; t++){
                float v = sB[r*FD + lane + 32*t];
                sa += v * sAs[lane + 32*t];
                sd += v * sAd[lane + 32*t];
            }
#pragma unroll
            for (int o = 16; o; o >>= 1){
                sa += __shfl_down_sync(0xffffffffu, sa, o);
                sd += __shfl_down_sync(0xffffffffu, sd, o);
            }
            if (lane == 0){ sAsrc[r] = sa; sAdst[r] = sd; }
        }
        __syncthreads();

        // fused logits + per-dest softmax: warp per node
        for (int nd = wrp; nd < NN; nd += 8){
            int beg = sOff[nd], end = sOff[nd+1];
            float adn = sAdst[nd];
            float m = -3.0e38f;
            for (int t = beg + lane; t < end; t += 32){
                int src = sSrc[t];
                float el = sAsrc[src] + adn;
                el = el > 0.f ? el : 0.2f * el;
                sAlpha[t] = el;
                m = fmaxf(m, el);
            }
#pragma unroll
            for (int o = 16; o; o >>= 1)
                m = fmaxf(m, __shfl_xor_sync(0xffffffffu, m, o));
            float s = 0.f;
            for (int t = beg + lane; t < end; t += 32){
                float w = __expf(sAlpha[t] - m);
                sAlpha[t] = w;
                s += w;
            }
#pragma unroll
            for (int o = 16; o; o >>= 1)
                s += __shfl_xor_sync(0xffffffffu, s, o);
            float inv = 1.f / s;
            for (int t = beg + lane; t < end; t += 32)
                sAlpha[t] *= inv;
        }
        __syncthreads();

        // aggregation: 128 col-pairs x 2 row halves; writes paired sA
        {
            const int p = tid & 127;
            const int q = tid >> 7;
            const float2* sB2 = reinterpret_cast<const float2*>(sB);
            float2 bbv = reinterpret_cast<const float2*>(bb)[p];
            for (int dd = q*26; dd < q*26 + 26; dd++){
                int beg = sOff[dd], end = sOff[dd+1];
                unsigned long long acc = 0ull;
                for (int t = beg; t < end; t++){
                    int src = sSrc[t];
                    float al = sAlpha[t];
                    F2U xv; xv.f = sB2[src*(FD/2) + p];
                    fma2(acc, xv.u, pack2(al, al));
                }
                float2 r = unpack2(acc);
                float v0 = r.x + bbv.x;
                float v1 = r.y + bbv.y;
                int a0 = (dd >> 1)*512 + 4*p + (dd & 1);
                if (rnd == 1){
                    v0 = fmaxf(v0 + sA[a0],     0.f);
                    v1 = fmaxf(v1 + sA[a0 + 2], 0.f);
                }
                sA[a0]     = v0;
                sA[a0 + 2] = v1;
            }
        }
        __syncthreads();
    }

    // ---------------- channel attention (thread = column) ----------------
    {
        const int j = tid;
        float s = 0.f, m = -3.0e38f;
#pragma unroll 4
        for (int r = 0; r < NN; r++){
            float v = sA[paddr(r, j)];
            s += v; m = fmaxf(m, v);
        }
        sAvg[j] = s * (1.f/52.f);
        sMx[j]  = m;
    }
    __syncthreads();
    {
        const int j = tid;
        float aA = 0.f, aM = 0.f;
        const float* wc = Wm + j;
#pragma unroll 4
        for (int k = 0; k < FD; k++){
            float w = wc[k*FD];
            aA += sAvg[k]*w;
            aM += sMx[k]*w;
        }
        float bj = bm[j];
        float mval = sigmoidf_(fmaxf(aA + bj, 0.f) + fmaxf(aM + bj, 0.f));
        __syncthreads();     // sAvg/sMx reads complete before sMch write zone reuse
        sMch[j] = mval;
    }
    __syncthreads();

    // ---------------- node attention ----------------
    for (int r = wrp; r < NN; r += 8){
        float mx = -3.0e38f;
#pragma unroll
        for (int t = 0; t < 8; t++){
            int f = lane + 32*t;
            mx = fmaxf(mx, sA[paddr(r, f)] * sMch[f]);
        }
#pragma unroll
        for (int o = 16; o; o >>= 1)
            mx = fmaxf(mx, __shfl_down_sync(0xffffffffu, mx, o));
        if (lane == 0) sHmax[r] = mx;
    }
    __syncthreads();
    if (tid < NN){
        float s = 0.f;
        int beg = sOff[tid], end = sOff[tid+1];
        for (int t = beg; t < end; t++){
            int ss = sSrc[t];
            s += sDinv[ss] * sHmax[ss];
        }
        float aggv = sDinv[tid] * s * wgp[0] + bgp[0];
        sMno[tid] = sigmoidf_(aggv);
    }
    __syncthreads();

    // ---------------- final write ----------------
    {
        float* op = outg + (size_t)g*NN*FD;
        for (int i = tid; i < NN*FD; i += NT){
            int r = i >> 8, f = i & 255;
            op[i] = sA[paddr(r, f)] * sMch[f] * sMno[r];
        }
    }
}

extern "C" void kernel_launch(void* const* d_in, const int* in_sizes, int n_in,
                              void* d_out, int out_size)
{
    const float* x   = (const float*)d_in[0];
    const void*  ei  = d_in[1];
    const float* W0  = (const float*)d_in[2];
    const float* as0 = (const float*)d_in[3];
    const float* ad0 = (const float*)d_in[4];
    const float* b0  = (const float*)d_in[5];
    const float* W1  = (const float*)d_in[6];
    const float* as1 = (const float*)d_in[7];
    const float* ad1 = (const float*)d_in[8];
    const float* b1  = (const float*)d_in[9];
    const float* Wm  = (const float*)d_in[10];
    const float* bm  = (const float*)d_in[11];
    const float* wg  = (const float*)d_in[12];
    const float* bg  = (const float*)d_in[13];
    float* out = (float*)d_out;

    int B = in_sizes[0] / (NN*FD);

    cudaFuncSetAttribute(gcab_kernel,
                         cudaFuncAttributeMaxDynamicSharedMemorySize,
                         SMEM_BYTES);
    gcab_kernel<<<B, NT, SMEM_BYTES>>>(x, ei, W0, as0, ad0, b0,
                                       W1, as1, ad1, b1, Wm, bm, wg, bg, out);
}

// round 9
// speedup vs baseline: 1.3791x; 1.0696x over previous
#include <cuda_runtime.h>

#define NN 52      // nodes
#define NE 832     // edges
#define E2 884     // edges + self loops
#define FD 256     // feature dim
#define NT 256     // threads per CTA (2 CTAs/SM)

union F2U { float2 f; unsigned long long u; };

__device__ __forceinline__ unsigned long long pack2(float a, float b){
    F2U t; t.f = make_float2(a, b); return t.u;
}
__device__ __forceinline__ float2 unpack2(unsigned long long v){
    F2U t; t.u = v; return t.f;
}
// packed dual-fp32 FMA (sm_100+)
__device__ __forceinline__ void fma2(unsigned long long& d,
                                     unsigned long long a,
                                     unsigned long long b){
    asm("fma.rn.f32x2 %0, %1, %2, %0;" : "+l"(d) : "l"(a), "l"(b));
}
__device__ __forceinline__ float sigmoidf_(float x){
    return 1.f / (1.f + __expf(-x));
}

// paired-row address: element (r, k) of the activation tile
__device__ __forceinline__ int paddr(int r, int k){
    return (r >> 1)*2*FD + 2*k + (r & 1);
}

// shared memory: sA(paired) + sB + alpha + src16 + as/ad + small + off
constexpr int SM_WORDS = NN*FD + NN*FD + E2 + (E2+1)/2 + FD*2 + NN*5 + (NN+1);
constexpr int SMEM_BYTES = SM_WORDS * 4;

__global__ void __launch_bounds__(NT, 2)
gcab_kernel(const float* __restrict__ xg, const void* __restrict__ eig,
            const float* __restrict__ W0, const float* __restrict__ as0,
            const float* __restrict__ ad0, const float* __restrict__ b0,
            const float* __restrict__ W1, const float* __restrict__ as1,
            const float* __restrict__ ad1, const float* __restrict__ b1,
            const float* __restrict__ Wm, const float* __restrict__ bm,
            const float* __restrict__ wgp, const float* __restrict__ bgp,
            float* __restrict__ outg)
{
    extern __shared__ float sm[];
    float* sA    = sm;                 // [26 pairs][512] paired-row activations
    float* sB    = sA + NN*FD;         // [52][256] xp row-major (+ overlays)
    float* sAlpha= sB + NN*FD;         // [884] edge alpha
    short* sSrc  = (short*)(sAlpha + E2);        // [884] src (int16)
    float* sAs   = sAlpha + E2 + (E2+1)/2;       // [256]
    float* sAd   = sAs + FD;           // [256]
    float* sAsrc = sAd + FD;           // [52]
    float* sAdst = sAsrc + NN;         // [52]
    float* sHmax = sAdst + NN;         // [52]
    float* sDinv = sHmax + NN;         // [52]
    float* sMno  = sDinv + NN;         // [52]
    int*   sOff  = (int*)(sMno + NN);  // [53]
    // setup-phase overlays inside sB
    int*   sS    = (int*)sB;           // [884]
    int*   sD    = sS + E2;            // [884]
    int*   sCnt  = sD + E2;            // [52]
    // epilogue-phase overlays inside sB
    float* sAvg  = sB;                 // [256]
    float* sMx   = sB + FD;            // [256]
    float* sMch  = sB + 2*FD;          // [256]
    __shared__ int sIs64;

    const int tid  = threadIdx.x;
    const int g    = blockIdx.x;
    const int lane = tid & 31, wrp = tid >> 5;

    // ------- detect edge_index dtype (int64 vs int32) -------
    if (tid == 0){
        const int* e32 = (const int*)eig;
        int flag = 1;
        #pragma unroll 1
        for (int i = 0; i < 32; i++){
            if (e32[2*i + 1] != 0){ flag = 0; break; }
        }
        sIs64 = flag;
    }

    // ---------------- load x into paired layout ----------------
    {
        const float* xr = xg + (size_t)g*NN*FD;
        for (int i = tid; i < NN*FD; i += NT){
            int r = i >> 8;
            int f = i & 255;
            sA[paddr(r, f)] = xr[i];
        }
        if (tid < NN) sCnt[tid] = 0;
    }
    __syncthreads();

    // ---------------- load edges (into sB overlay) ----------------
    {
        const int is64 = sIs64;
        const long long* ei64 = (const long long*)eig + (size_t)g*2*NE;
        const int*       ei32 = (const int*)eig       + (size_t)g*2*NE;
        for (int e = tid; e < E2; e += NT){
            int s, d;
            if (e < NE){
                if (is64){ s = (int)ei64[e]; d = (int)ei64[NE + e]; }
                else     { s = ei32[e];      d = ei32[NE + e]; }
            } else {
                s = e - NE; d = e - NE;
            }
            sS[e] = s; sD[e] = d;
        }
    }
    __syncthreads();
    for (int e = tid; e < E2; e += NT) atomicAdd(&sCnt[sD[e]], 1);
    __syncthreads();
    if (tid == 0){
        int acc = 0;
        for (int i = 0; i < NN; i++){ sOff[i] = acc; acc += sCnt[i]; }
        sOff[NN] = acc;
    }
    if (tid >= 32 && tid < 32 + NN) sDinv[tid-32] = rsqrtf((float)sCnt[tid-32]);
    __syncthreads();
    // deterministic CSR fill: 7 nodes per warp (8 warps), writes int16 src
    {
        int nds[7], poss[7];
#pragma unroll
        for (int j = 0; j < 7; j++){
            nds[j]  = wrp + 8*j;
            poss[j] = (nds[j] < NN) ? sOff[nds[j]] : 0;
        }
        const unsigned lt = (1u << lane) - 1u;
        for (int base = 0; base < E2; base += 32){
            int e = base + lane;
            int d = -1, s = 0;
            if (e < E2){ d = sD[e]; s = sS[e]; }
#pragma unroll
            for (int j = 0; j < 7; j++){
                unsigned m = __ballot_sync(0xffffffffu, d == nds[j]);
                if (d == nds[j]) sSrc[poss[j] + __popc(m & lt)] = (short)s;
                poss[j] += __popc(m);
            }
        }
    }
    __syncthreads();

    // GEMM thread mapping: 64 col-quads x 4 row-groups of 13 rows
    const int colq = tid & 63;       // cols 4*colq .. 4*colq+3
    const int rq   = tid >> 6;       // rows rq*13 .. rq*13+12
    const int rbase = rq*13;
    // row group = 6 even-odd pairs + 1 scalar row
    const int pstart = (rbase & 1) ? rbase + 1  : rbase;       // even
    const int srow   = (rbase & 1) ? rbase      : rbase + 12;

    // ---------------- two GAT rounds ----------------
    for (int rnd = 0; rnd < 2; rnd++){
        const float* W  = rnd ? W1  : W0;
        const float* av = rnd ? as1 : as0;
        const float* dv = rnd ? ad1 : ad0;
        const float* bb = rnd ? b1  : b0;
        for (int i = tid; i < FD; i += NT){ sAs[i] = av[i]; sAd[i] = dv[i]; }
        __syncthreads();   // sB (epilogue overlay / old xp) reuse barrier

        // GEMM: sB[52][256] = A[52][256] @ W[256][256]
        // thread tile: 13 rows x 4 cols; A delivered 52B/k (halved)
        {
            unsigned long long accp[6][4];   // row-pairs x 4 cols (lanes=rows)
            unsigned long long accs[2];      // scalar row, cols packed
#pragma unroll
            for (int i = 0; i < 6; i++)
#pragma unroll
                for (int c = 0; c < 4; c++) accp[i][c] = 0ull;
            accs[0] = accs[1] = 0ull;

            const float* wb0 = W + 4*colq;
            const float2* xp = reinterpret_cast<const float2*>(sA) + (pstart >> 1)*FD;
            const float*  xs = sA + (srow >> 1)*2*FD + (srow & 1);

            float4 wA[4], wB[4];
#pragma unroll
            for (int j = 0; j < 4; j++)
                wA[j] = *reinterpret_cast<const float4*>(wb0 + (size_t)j*FD);

#pragma unroll 1
            for (int kb = 0; kb < 256; kb += 8){
                // prefetch bank B: k = kb+4 .. kb+7
#pragma unroll
                for (int j = 0; j < 4; j++)
                    wB[j] = *reinterpret_cast<const float4*>(wb0 + (size_t)(kb+4+j)*FD);
                // process bank A
#pragma unroll
                for (int j = 0; j < 4; j++){
                    const int k = kb + j;
                    float4 w = wA[j];
                    unsigned long long wsp[4];
                    wsp[0] = pack2(w.x, w.x);
                    wsp[1] = pack2(w.y, w.y);
                    wsp[2] = pack2(w.z, w.z);
                    wsp[3] = pack2(w.w, w.w);
#pragma unroll
                    for (int i = 0; i < 6; i++){
                        F2U xv; xv.f = xp[i*FD + k];
#pragma unroll
                        for (int c = 0; c < 4; c++)
                            fma2(accp[i][c], xv.u, wsp[c]);
                    }
                    {
                        float xsv = xs[2*k];
                        unsigned long long xd = pack2(xsv, xsv);
                        F2U b0v; b0v.f = make_float2(w.x, w.y);
                        F2U b1v; b1v.f = make_float2(w.z, w.w);
                        fma2(accs[0], xd, b0v.u);
                        fma2(accs[1], xd, b1v.u);
                    }
                }
                // prefetch bank A: k = kb+8 .. kb+11 (clamped)
                {
                    int kn = (kb + 8 < 256) ? (kb + 8) : 0;
#pragma unroll
                    for (int j = 0; j < 4; j++)
                        wA[j] = *reinterpret_cast<const float4*>(wb0 + (size_t)(kn+j)*FD);
                }
                // process bank B
#pragma unroll
                for (int j = 0; j < 4; j++){
                    const int k = kb + 4 + j;
                    float4 w = wB[j];
                    unsigned long long wsp[4];
                    wsp[0] = pack2(w.x, w.x);
                    wsp[1] = pack2(w.y, w.y);
                    wsp[2] = pack2(w.z, w.z);
                    wsp[3] = pack2(w.w, w.w);
#pragma unroll
                    for (int i = 0; i < 6; i++){
                        F2U xv; xv.f = xp[i*FD + k];
#pragma unroll
                        for (int c = 0; c < 4; c++)
                            fma2(accp[i][c], xv.u, wsp[c]);
                    }
                    {
                        float xsv = xs[2*k];
                        unsigned long long xd = pack2(xsv, xsv);
                        F2U b0v; b0v.f = make_float2(w.x, w.y);
                        F2U b1v; b1v.f = make_float2(w.z, w.w);
                        fma2(accs[0], xd, b0v.u);
                        fma2(accs[1], xd, b1v.u);
                    }
                }
            }
            // store: pair rows as float4 (cols 4colq..+3)
#pragma unroll
            for (int i = 0; i < 6; i++){
                float2 c0 = unpack2(accp[i][0]);
                float2 c1 = unpack2(accp[i][1]);
                float2 c2 = unpack2(accp[i][2]);
                float2 c3 = unpack2(accp[i][3]);
                int r0 = pstart + 2*i;
                reinterpret_cast<float4*>(sB + r0*FD)[colq] =
                    make_float4(c0.x, c1.x, c2.x, c3.x);
                reinterpret_cast<float4*>(sB + (r0+1)*FD)[colq] =
                    make_float4(c0.y, c1.y, c2.y, c3.y);
            }
            {
                float2 a0 = unpack2(accs[0]);
                float2 a1 = unpack2(accs[1]);
                reinterpret_cast<float4*>(sB + srow*FD)[colq] =
                    make_float4(a0.x, a0.y, a1.x, a1.y);
            }
        }
        __syncthreads();

        // asrc/adst per row: warp-per-row (8 warps)
        for (int r = wrp; r < NN; r += 8){
            float sa = 0.f, sd = 0.f;
#pragma unroll
            for (int t = 0; t < 8; t++){
                float v = sB[r*FD + lane + 32*t];
                sa += v * sAs[lane + 32*t];
                sd += v * sAd[lane + 32*t];
            }
#pragma unroll
            for (int o = 16; o; o >>= 1){
                sa += __shfl_down_sync(0xffffffffu, sa, o);
                sd += __shfl_down_sync(0xffffffffu, sd, o);
            }
            if (lane == 0){ sAsrc[r] = sa; sAdst[r] = sd; }
        }
        __syncthreads();

        // fused logits + per-dest softmax: warp per node
        for (int nd = wrp; nd < NN; nd += 8){
            int beg = sOff[nd], end = sOff[nd+1];
            float adn = sAdst[nd];
            float m = -3.0e38f;
            for (int t = beg + lane; t < end; t += 32){
                int src = sSrc[t];
                float el = sAsrc[src] + adn;
                el = el > 0.f ? el : 0.2f * el;
                sAlpha[t] = el;
                m = fmaxf(m, el);
            }
#pragma unroll
            for (int o = 16; o; o >>= 1)
                m = fmaxf(m, __shfl_xor_sync(0xffffffffu, m, o));
            float s = 0.f;
            for (int t = beg + lane; t < end; t += 32){
                float w = __expf(sAlpha[t] - m);
                sAlpha[t] = w;
                s += w;
            }
#pragma unroll
            for (int o = 16; o; o >>= 1)
                s += __shfl_xor_sync(0xffffffffu, s, o);
            float inv = 1.f / s;
            for (int t = beg + lane; t < end; t += 32)
                sAlpha[t] *= inv;
        }
        __syncthreads();

        // aggregation: 128 col-pairs x 2 row halves; writes paired sA
        {
            const int p = tid & 127;
            const int q = tid >> 7;
            const float2* sB2 = reinterpret_cast<const float2*>(sB);
            float2 bbv = reinterpret_cast<const float2*>(bb)[p];
            for (int dd = q*26; dd < q*26 + 26; dd++){
                int beg = sOff[dd], end = sOff[dd+1];
                unsigned long long acc = 0ull;
                for (int t = beg; t < end; t++){
                    int src = sSrc[t];
                    float al = sAlpha[t];
                    F2U xv; xv.f = sB2[src*(FD/2) + p];
                    fma2(acc, xv.u, pack2(al, al));
                }
                float2 r = unpack2(acc);
                float v0 = r.x + bbv.x;
                float v1 = r.y + bbv.y;
                int a0 = (dd >> 1)*512 + 4*p + (dd & 1);
                if (rnd == 1){
                    v0 = fmaxf(v0 + sA[a0],     0.f);
                    v1 = fmaxf(v1 + sA[a0 + 2], 0.f);
                }
                sA[a0]     = v0;
                sA[a0 + 2] = v1;
            }
        }
        __syncthreads();
    }

    // ---------------- channel attention (thread = column) ----------------
    {
        const int j = tid;
        float s = 0.f, m = -3.0e38f;
#pragma unroll 4
        for (int r = 0; r < NN; r++){
            float v = sA[paddr(r, j)];
            s += v; m = fmaxf(m, v);
        }
        sAvg[j] = s * (1.f/52.f);
        sMx[j]  = m;
    }
    __syncthreads();
    {
        const int j = tid;
        float aA = 0.f, aM = 0.f;
        const float* wc = Wm + j;
#pragma unroll 4
        for (int k = 0; k < FD; k++){
            float w = wc[k*FD];
            aA += sAvg[k]*w;
            aM += sMx[k]*w;
        }
        float bj = bm[j];
        float mval = sigmoidf_(fmaxf(aA + bj, 0.f) + fmaxf(aM + bj, 0.f));
        __syncthreads();     // sAvg/sMx reads complete before sMch write zone reuse
        sMch[j] = mval;
    }
    __syncthreads();

    // ---------------- node attention ----------------
    for (int r = wrp; r < NN; r += 8){
        float mx = -3.0e38f;
#pragma unroll
        for (int t = 0; t < 8; t++){
            int f = lane + 32*t;
            mx = fmaxf(mx, sA[paddr(r, f)] * sMch[f]);
        }
#pragma unroll
        for (int o = 16; o; o >>= 1)
            mx = fmaxf(mx, __shfl_down_sync(0xffffffffu, mx, o));
        if (lane == 0) sHmax[r] = mx;
    }
    __syncthreads();
    if (tid < NN){
        float s = 0.f;
        int beg = sOff[tid], end = sOff[tid+1];
        for (int t = beg; t < end; t++){
            int ss = sSrc[t];
            s += sDinv[ss] * sHmax[ss];
        }
        float aggv = sDinv[tid] * s * wgp[0] + bgp[0];
        sMno[tid] = sigmoidf_(aggv);
    }
    __syncthreads();

    // ---------------- final write ----------------
    {
        float* op = outg + (size_t)g*NN*FD;
        for (int i = tid; i < NN*FD; i += NT){
            int r = i >> 8, f = i & 255;
            op[i] = sA[paddr(r, f)] * sMch[f] * sMno[r];
        }
    }
}

extern "C" void kernel_launch(void* const* d_in, const int* in_sizes, int n_in,
                              void* d_out, int out_size)
{
    const float* x   = (const float*)d_in[0];
    const void*  ei  = d_in[1];
    const float* W0  = (const float*)d_in[2];
    const float* as0 = (const float*)d_in[3];
    const float* ad0 = (const float*)d_in[4];
    const float* b0  = (const float*)d_in[5];
    const float* W1  = (const float*)d_in[6];
    const float* as1 = (const float*)d_in[7];
    const float* ad1 = (const float*)d_in[8];
    const float* b1  = (const float*)d_in[9];
    const float* Wm  = (const float*)d_in[10];
    const float* bm  = (const float*)d_in[11];
    const float* wg  = (const float*)d_in[12];
    const float* bg  = (const float*)d_in[13];
    float* out = (float*)d_out;

    int B = in_sizes[0] / (NN*FD);

    cudaFuncSetAttribute(gcab_kernel,
                         cudaFuncAttributeMaxDynamicSharedMemorySize,
                         SMEM_BYTES);
    gcab_kernel<<<B, NT, SMEM_BYTES>>>(x, ei, W0, as0, ad0, b0,
                                       W1, as1, ad1, b1, Wm, bm, wg, bg, out);
}

// round 10
// speedup vs baseline: 1.3996x; 1.0148x over previous
#include <cuda_runtime.h>

#define NN 52      // nodes
#define NE 832     // edges
#define E2 884     // edges + self loops
#define FD 256     // feature dim
#define NT 256     // threads per CTA (2 CTAs/SM)

union F2U { float2 f; unsigned long long u; };

__device__ __forceinline__ unsigned long long pack2(float a, float b){
    F2U t; t.f = make_float2(a, b); return t.u;
}
__device__ __forceinline__ float2 unpack2(unsigned long long v){
    F2U t; t.u = v; return t.f;
}
// packed dual-fp32 FMA (sm_100+)
__device__ __forceinline__ void fma2(unsigned long long& d,
                                     unsigned long long a,
                                     unsigned long long b){
    asm("fma.rn.f32x2 %0, %1, %2, %0;" : "+l"(d) : "l"(a), "l"(b));
}
__device__ __forceinline__ float sigmoidf_(float x){
    return 1.f / (1.f + __expf(-x));
}

// paired-row address: element (r, k) of the activation tile
__device__ __forceinline__ int paddr(int r, int k){
    return (r >> 1)*2*FD + 2*k + (r & 1);
}

// shared memory: sA(paired) + sB + alpha + src16 + as/ad + small + off
constexpr int SM_WORDS = NN*FD + NN*FD + E2 + (E2+1)/2 + FD*2 + NN*5 + (NN+1);
constexpr int SMEM_BYTES = SM_WORDS * 4;

__global__ void __launch_bounds__(NT, 2)
gcab_kernel(const float* __restrict__ xg, const void* __restrict__ eig,
            const float* __restrict__ W0, const float* __restrict__ as0,
            const float* __restrict__ ad0, const float* __restrict__ b0,
            const float* __restrict__ W1, const float* __restrict__ as1,
            const float* __restrict__ ad1, const float* __restrict__ b1,
            const float* __restrict__ Wm, const float* __restrict__ bm,
            const float* __restrict__ wgp, const float* __restrict__ bgp,
            float* __restrict__ outg)
{
    extern __shared__ float sm[];
    float* sA    = sm;                 // [26 pairs][512] paired-row activations
    float* sB    = sA + NN*FD;         // [52][256] xp row-major (+ overlays)
    float* sAlpha= sB + NN*FD;         // [884] edge alpha
    short* sSrc  = (short*)(sAlpha + E2);        // [884] src (int16)
    float* sAs   = sAlpha + E2 + (E2+1)/2;       // [256]
    float* sAd   = sAs + FD;           // [256]
    float* sAsrc = sAd + FD;           // [52]
    float* sAdst = sAsrc + NN;         // [52]
    float* sHmax = sAdst + NN;         // [52]
    float* sDinv = sHmax + NN;         // [52]
    float* sMno  = sDinv + NN;         // [52]
    int*   sOff  = (int*)(sMno + NN);  // [53]
    // setup-phase overlays inside sB
    int*   sS    = (int*)sB;           // [884]
    int*   sD    = sS + E2;            // [884]
    int*   sCnt  = sD + E2;            // [52]
    // epilogue-phase overlays inside sB
    float* sAvg  = sB;                 // [256]
    float* sMx   = sB + FD;            // [256]
    float* sMch  = sB + 2*FD;          // [256]
    __shared__ int sIs64;

    const int tid  = threadIdx.x;
    const int g    = blockIdx.x;
    const int lane = tid & 31, wrp = tid >> 5;

    // ------- detect edge_index dtype (int64 vs int32) -------
    if (tid == 0){
        const int* e32 = (const int*)eig;
        int flag = 1;
        #pragma unroll 1
        for (int i = 0; i < 32; i++){
            if (e32[2*i + 1] != 0){ flag = 0; break; }
        }
        sIs64 = flag;
    }

    // ---------------- load x into paired layout ----------------
    {
        const float* xr = xg + (size_t)g*NN*FD;
        for (int i = tid; i < NN*FD; i += NT){
            int r = i >> 8;
            int f = i & 255;
            sA[paddr(r, f)] = xr[i];
        }
        if (tid < NN) sCnt[tid] = 0;
    }
    __syncthreads();

    // ---------------- load edges (into sB overlay) ----------------
    {
        const int is64 = sIs64;
        const long long* ei64 = (const long long*)eig + (size_t)g*2*NE;
        const int*       ei32 = (const int*)eig       + (size_t)g*2*NE;
        for (int e = tid; e < E2; e += NT){
            int s, d;
            if (e < NE){
                if (is64){ s = (int)ei64[e]; d = (int)ei64[NE + e]; }
                else     { s = ei32[e];      d = ei32[NE + e]; }
            } else {
                s = e - NE; d = e - NE;
            }
            sS[e] = s; sD[e] = d;
        }
    }
    __syncthreads();
    for (int e = tid; e < E2; e += NT) atomicAdd(&sCnt[sD[e]], 1);
    __syncthreads();
    if (tid == 0){
        int acc = 0;
        for (int i = 0; i < NN; i++){ sOff[i] = acc; acc += sCnt[i]; }
        sOff[NN] = acc;
    }
    if (tid >= 32 && tid < 32 + NN) sDinv[tid-32] = rsqrtf((float)sCnt[tid-32]);
    __syncthreads();
    // deterministic CSR fill: 7 nodes per warp (8 warps), writes int16 src
    {
        int nds[7], poss[7];
#pragma unroll
        for (int j = 0; j < 7; j++){
            nds[j]  = wrp + 8*j;
            poss[j] = (nds[j] < NN) ? sOff[nds[j]] : 0;
        }
        const unsigned lt = (1u << lane) - 1u;
        for (int base = 0; base < E2; base += 32){
            int e = base + lane;
            int d = -1, s = 0;
            if (e < E2){ d = sD[e]; s = sS[e]; }
#pragma unroll
            for (int j = 0; j < 7; j++){
                unsigned m = __ballot_sync(0xffffffffu, d == nds[j]);
                if (d == nds[j]) sSrc[poss[j] + __popc(m & lt)] = (short)s;
                poss[j] += __popc(m);
            }
        }
    }
    __syncthreads();

    // GEMM thread mapping: 64 col-quads x 4 row-groups of 13 rows
    const int colq = tid & 63;       // cols 4*colq .. 4*colq+3
    const int rq   = tid >> 6;       // rows rq*13 .. rq*13+12
    const int rbase = rq*13;
    // row group = 6 even-odd pairs + 1 scalar row
    const int pstart = (rbase & 1) ? rbase + 1  : rbase;       // even
    const int srow   = (rbase & 1) ? rbase      : rbase + 12;

    // ---------------- two GAT rounds ----------------
    for (int rnd = 0; rnd < 2; rnd++){
        const float* W  = rnd ? W1  : W0;
        const float* av = rnd ? as1 : as0;
        const float* dv = rnd ? ad1 : ad0;
        const float* bb = rnd ? b1  : b0;
        for (int i = tid; i < FD; i += NT){ sAs[i] = av[i]; sAd[i] = dv[i]; }
        __syncthreads();   // sB (epilogue overlay / old xp) reuse barrier

        // GEMM: sB[52][256] = A[52][256] @ W[256][256]
        // thread tile: 13 rows x 4 cols; A delivered 52B/k
        {
            unsigned long long accp[6][4];   // row-pairs x 4 cols (lanes=rows)
            unsigned long long accs[2];      // scalar row, cols packed
#pragma unroll
            for (int i = 0; i < 6; i++)
#pragma unroll
                for (int c = 0; c < 4; c++) accp[i][c] = 0ull;
            accs[0] = accs[1] = 0ull;

            const float* wb0 = W + 4*colq;
            const float2* xp = reinterpret_cast<const float2*>(sA) + (pstart >> 1)*FD;
            const float*  xs = sA + (srow >> 1)*2*FD + (srow & 1);

            float4 wA[4], wB[4];
#pragma unroll
            for (int j = 0; j < 4; j++)
                wA[j] = *reinterpret_cast<const float4*>(wb0 + (size_t)j*FD);

#pragma unroll 1
            for (int kb = 0; kb < 256; kb += 8){
                // prefetch bank B: k = kb+4 .. kb+7
#pragma unroll
                for (int j = 0; j < 4; j++)
                    wB[j] = *reinterpret_cast<const float4*>(wb0 + (size_t)(kb+4+j)*FD);
                // process bank A
#pragma unroll
                for (int j = 0; j < 4; j++){
                    const int k = kb + j;
                    float4 w = wA[j];
                    unsigned long long wsp[4];
                    wsp[0] = pack2(w.x, w.x);
                    wsp[1] = pack2(w.y, w.y);
                    wsp[2] = pack2(w.z, w.z);
                    wsp[3] = pack2(w.w, w.w);
#pragma unroll
                    for (int i = 0; i < 6; i++){
                        F2U xv; xv.f = xp[i*FD + k];
#pragma unroll
                        for (int c = 0; c < 4; c++)
                            fma2(accp[i][c], xv.u, wsp[c]);
                    }
                    {
                        float xsv = xs[2*k];
                        unsigned long long xd = pack2(xsv, xsv);
                        F2U b0v; b0v.f = make_float2(w.x, w.y);
                        F2U b1v; b1v.f = make_float2(w.z, w.w);
                        fma2(accs[0], xd, b0v.u);
                        fma2(accs[1], xd, b1v.u);
                    }
                }
                // prefetch bank A: k = kb+8 .. kb+11 (clamped)
                {
                    int kn = (kb + 8 < 256) ? (kb + 8) : 0;
#pragma unroll
                    for (int j = 0; j < 4; j++)
                        wA[j] = *reinterpret_cast<const float4*>(wb0 + (size_t)(kn+j)*FD);
                }
                // process bank B
#pragma unroll
                for (int j = 0; j < 4; j++){
                    const int k = kb + 4 + j;
                    float4 w = wB[j];
                    unsigned long long wsp[4];
                    wsp[0] = pack2(w.x, w.x);
                    wsp[1] = pack2(w.y, w.y);
                    wsp[2] = pack2(w.z, w.z);
                    wsp[3] = pack2(w.w, w.w);
#pragma unroll
                    for (int i = 0; i < 6; i++){
                        F2U xv; xv.f = xp[i*FD + k];
#pragma unroll
                        for (int c = 0; c < 4; c++)
                            fma2(accp[i][c], xv.u, wsp[c]);
                    }
                    {
                        float xsv = xs[2*k];
                        unsigned long long xd = pack2(xsv, xsv);
                        F2U b0v; b0v.f = make_float2(w.x, w.y);
                        F2U b1v; b1v.f = make_float2(w.z, w.w);
                        fma2(accs[0], xd, b0v.u);
                        fma2(accs[1], xd, b1v.u);
                    }
                }
            }
            // store: pair rows as float4 (cols 4colq..+3)
#pragma unroll
            for (int i = 0; i < 6; i++){
                float2 c0 = unpack2(accp[i][0]);
                float2 c1 = unpack2(accp[i][1]);
                float2 c2 = unpack2(accp[i][2]);
                float2 c3 = unpack2(accp[i][3]);
                int r0 = pstart + 2*i;
                reinterpret_cast<float4*>(sB + r0*FD)[colq] =
                    make_float4(c0.x, c1.x, c2.x, c3.x);
                reinterpret_cast<float4*>(sB + (r0+1)*FD)[colq] =
                    make_float4(c0.y, c1.y, c2.y, c3.y);
            }
            {
                float2 a0 = unpack2(accs[0]);
                float2 a1 = unpack2(accs[1]);
                reinterpret_cast<float4*>(sB + srow*FD)[colq] =
                    make_float4(a0.x, a0.y, a1.x, a1.y);
            }
        }
        __syncthreads();

        // asrc/adst per row: warp-per-row, a_s/a_d cached in regs, packed fma2
        {
            const float2* sAs2 = reinterpret_cast<const float2*>(sAs);
            const float2* sAd2 = reinterpret_cast<const float2*>(sAd);
            F2U avr[4], dvr[4];
#pragma unroll
            for (int t = 0; t < 4; t++){
                avr[t].f = sAs2[lane + 32*t];
                dvr[t].f = sAd2[lane + 32*t];
            }
            for (int r = wrp; r < NN; r += 8){
                const float2* vb = reinterpret_cast<const float2*>(sB + r*FD);
                unsigned long long sa2 = 0ull, sd2 = 0ull;
#pragma unroll
                for (int t = 0; t < 4; t++){
                    F2U v; v.f = vb[lane + 32*t];
                    fma2(sa2, v.u, avr[t].u);
                    fma2(sd2, v.u, dvr[t].u);
                }
                float2 sap = unpack2(sa2), sdp = unpack2(sd2);
                float sa = sap.x + sap.y, sd = sdp.x + sdp.y;
#pragma unroll
                for (int o = 16; o; o >>= 1){
                    sa += __shfl_down_sync(0xffffffffu, sa, o);
                    sd += __shfl_down_sync(0xffffffffu, sd, o);
                }
                if (lane == 0){ sAsrc[r] = sa; sAdst[r] = sd; }
            }
        }
        __syncthreads();

        // fused logits + per-dest softmax: warp per node
        for (int nd = wrp; nd < NN; nd += 8){
            int beg = sOff[nd], end = sOff[nd+1];
            float adn = sAdst[nd];
            float m = -3.0e38f;
            for (int t = beg + lane; t < end; t += 32){
                int src = sSrc[t];
                float el = sAsrc[src] + adn;
                el = el > 0.f ? el : 0.2f * el;
                sAlpha[t] = el;
                m = fmaxf(m, el);
            }
#pragma unroll
            for (int o = 16; o; o >>= 1)
                m = fmaxf(m, __shfl_xor_sync(0xffffffffu, m, o));
            float s = 0.f;
            for (int t = beg + lane; t < end; t += 32){
                float w = __expf(sAlpha[t] - m);
                sAlpha[t] = w;
                s += w;
            }
#pragma unroll
            for (int o = 16; o; o >>= 1)
                s += __shfl_xor_sync(0xffffffffu, s, o);
            float inv = 1.f / s;
            for (int t = beg + lane; t < end; t += 32)
                sAlpha[t] *= inv;
        }
        __syncthreads();

        // aggregation: pairwise edges (1 LDS.32 srcs + 1 LDS.64 alphas / 2 edges)
        {
            const int p = tid & 127;
            const int q = tid >> 7;
            const float2* sB2 = reinterpret_cast<const float2*>(sB);
            float2 bbv = reinterpret_cast<const float2*>(bb)[p];
            for (int dd = q*26; dd < q*26 + 26; dd++){
                int beg = sOff[dd], end = sOff[dd+1];
                unsigned long long acc = 0ull;
                int t = beg;
                if (t & 1){
                    int src = sSrc[t];
                    float al = sAlpha[t];
                    F2U xv; xv.f = sB2[src*(FD/2) + p];
                    fma2(acc, xv.u, pack2(al, al));
                    t++;
                }
#pragma unroll 2
                for (; t + 1 < end; t += 2){
                    int spair = *reinterpret_cast<const int*>(&sSrc[t]);
                    int s0 = spair & 0xffff;
                    int s1 = (spair >> 16) & 0xffff;
                    float2 al2 = *reinterpret_cast<const float2*>(&sAlpha[t]);
                    F2U x0; x0.f = sB2[s0*(FD/2) + p];
                    F2U x1; x1.f = sB2[s1*(FD/2) + p];
                    fma2(acc, x0.u, pack2(al2.x, al2.x));
                    fma2(acc, x1.u, pack2(al2.y, al2.y));
                }
                if (t < end){
                    int src = sSrc[t];
                    float al = sAlpha[t];
                    F2U xv; xv.f = sB2[src*(FD/2) + p];
                    fma2(acc, xv.u, pack2(al, al));
                }
                float2 r = unpack2(acc);
                float v0 = r.x + bbv.x;
                float v1 = r.y + bbv.y;
                int a0 = (dd >> 1)*512 + 4*p + (dd & 1);
                if (rnd == 1){
                    v0 = fmaxf(v0 + sA[a0],     0.f);
                    v1 = fmaxf(v1 + sA[a0 + 2], 0.f);
                }
                sA[a0]     = v0;
                sA[a0 + 2] = v1;
            }
        }
        __syncthreads();
    }

    // ---------------- channel attention (thread = column) ----------------
    {
        const int j = tid;
        float s = 0.f, m = -3.0e38f;
#pragma unroll 4
        for (int r = 0; r < NN; r++){
            float v = sA[paddr(r, j)];
            s += v; m = fmaxf(m, v);
        }
        sAvg[j] = s * (1.f/52.f);
        sMx[j]  = m;
    }
    __syncthreads();
    {
        const int j = tid;
        float aA = 0.f, aM = 0.f;
        const float* wc = Wm + j;
#pragma unroll 4
        for (int k = 0; k < FD; k++){
            float w = wc[k*FD];
            aA += sAvg[k]*w;
            aM += sMx[k]*w;
        }
        float bj = bm[j];
        float mval = sigmoidf_(fmaxf(aA + bj, 0.f) + fmaxf(aM + bj, 0.f));
        __syncthreads();     // sAvg/sMx reads complete before sMch write zone reuse
        sMch[j] = mval;
    }
    __syncthreads();

    // ---------------- node attention ----------------
    for (int r = wrp; r < NN; r += 8){
        float mx = -3.0e38f;
#pragma unroll
        for (int t = 0; t < 8; t++){
            int f = lane + 32*t;
            mx = fmaxf(mx, sA[paddr(r, f)] * sMch[f]);
        }
#pragma unroll
        for (int o = 16; o; o >>= 1)
            mx = fmaxf(mx, __shfl_down_sync(0xffffffffu, mx, o));
        if (lane == 0) sHmax[r] = mx;
    }
    __syncthreads();
    if (tid < NN){
        float s = 0.f;
        int beg = sOff[tid], end = sOff[tid+1];
        for (int t = beg; t < end; t++){
            int ss = sSrc[t];
            s += sDinv[ss] * sHmax[ss];
        }
        float aggv = sDinv[tid] * s * wgp[0] + bgp[0];
        sMno[tid] = sigmoidf_(aggv);
    }
    __syncthreads();

    // ---------------- final write (f = tid invariant; mch hoisted) ----------------
    {
        float* op = outg + (size_t)g*NN*FD + tid;
        float mch = sMch[tid];
        const float* ap = sA + 2*tid;
#pragma unroll 4
        for (int r = 0; r < NN; r++){
            op[r*FD] = ap[(r >> 1)*512 + (r & 1)] * mch * sMno[r];
        }
    }
}

extern "C" void kernel_launch(void* const* d_in, const int* in_sizes, int n_in,
                              void* d_out, int out_size)
{
    const float* x   = (const float*)d_in[0];
    const void*  ei  = d_in[1];
    const float* W0  = (const float*)d_in[2];
    const float* as0 = (const float*)d_in[3];
    const float* ad0 = (const float*)d_in[4];
    const float* b0  = (const float*)d_in[5];
    const float* W1  = (const float*)d_in[6];
    const float* as1 = (const float*)d_in[7];
    const float* ad1 = (const float*)d_in[8];
    const float* b1  = (const float*)d_in[9];
    const float* Wm  = (const float*)d_in[10];
    const float* bm  = (const float*)d_in[11];
    const float* wg  = (const float*)d_in[12];
    const float* bg  = (const float*)d_in[13];
    float* out = (float*)d_out;

    int B = in_sizes[0] / (NN*FD);

    cudaFuncSetAttribute(gcab_kernel,
                         cudaFuncAttributeMaxDynamicSharedMemorySize,
                         SMEM_BYTES);
    gcab_kernel<<<B, NT, SMEM_BYTES>>>(x, ei, W0, as0, ad0, b0,
                                       W1, as1, ad1, b1, Wm, bm, wg, bg, out);
}